// round 7
// baseline (speedup 1.0000x reference)
#include <cuda_runtime.h>
#include <math.h>

// Problem constants (fixed by the dataset)
#define LDIM 128        // nodes per sentence
#define HDIM 128        // hidden
#define NBS  2048       // B*S sentences
#define SST  132        // smem row stride (pad to dodge conflicts)
#define NUM_LOOP 10

// ---------------- device scratch (no cudaMalloc allowed) ----------------
__device__ float g_Gt[128 * 384];    // (gnn_w @ W_ih^T), row-major [k][j]
__device__ float g_Whht[128 * 384];  // W_hh^T, [k][j] = W_hh[j][k]
__device__ float g_u[384];           // gnn_b @ W_ih^T
__device__ float g_m1t[128 * 128];   // mW1^T
__device__ float g_m2t[128 * 128];   // mW2^T

// ---------------- prep kernels (run every launch; deterministic) --------
__global__ void prep_gemm(const float* __restrict__ gnn_w,
                          const float* __restrict__ W_ih,
                          const float* __restrict__ gnn_b) {
    int t = blockIdx.x * blockDim.x + threadIdx.x;
    if (t < 128 * 384) {
        int k = t / 384, j = t % 384;
        const float* wr = gnn_w + k * 128;
        const float* ir = W_ih + j * 128;
        float acc = 0.f;
#pragma unroll 4
        for (int m = 0; m < 128; ++m) acc = fmaf(wr[m], ir[m], acc);
        g_Gt[t] = acc;
        if (t < 384) {
            const float* ir2 = W_ih + t * 128;
            float a2 = 0.f;
#pragma unroll 4
            for (int m = 0; m < 128; ++m) a2 = fmaf(gnn_b[m], ir2[m], a2);
            g_u[t] = a2;
        }
    }
}

__global__ void prep_trans(const float* __restrict__ W_hh,
                           const float* __restrict__ mW1,
                           const float* __restrict__ mW2) {
    int t = blockIdx.x * blockDim.x + threadIdx.x;
    if (t < 128 * 384) {
        int k = t / 384, j = t % 384;
        g_Whht[t] = W_hh[j * 128 + k];
    } else if (t < 128 * 384 + 128 * 128) {
        int q = t - 128 * 384;
        int k = q / 128, j = q % 128;
        g_m1t[q] = mW1[j * 128 + k];
    } else if (t < 128 * 384 + 2 * 128 * 128) {
        int q = t - 128 * 384 - 128 * 128;
        int k = q / 128, j = q % 128;
        g_m2t[q] = mW2[j * 128 + k];
    }
}

// ---------------- register-tiled GEMM: C[128,128] += A_smem[128,128] @ B_glb[128,ldb] ----
// Thread (tx,ty) in 16x16 grid owns 8x8 C tile: rows ty*8.., cols tx*8..
__device__ __forceinline__ void gemm1(const float* __restrict__ A,
                                      const float* __restrict__ B,
                                      int ldb,
                                      float* __restrict__ acc,
                                      int tx, int ty) {
    const float* Ar = A + ty * 8 * SST;
    const float* Bp = B + tx * 8;
#pragma unroll 2
    for (int k4 = 0; k4 < 128; k4 += 4) {
        float4 a4[8];
#pragma unroll
        for (int i = 0; i < 8; ++i)
            a4[i] = *(const float4*)(Ar + i * SST + k4);
        float4 b0[4], b1[4];
#pragma unroll
        for (int kk = 0; kk < 4; ++kk) {
            b0[kk] = *(const float4*)(Bp + (k4 + kk) * ldb);
            b1[kk] = *(const float4*)(Bp + (k4 + kk) * ldb + 4);
        }
#pragma unroll
        for (int kk = 0; kk < 4; ++kk) {
            float b[8] = {b0[kk].x, b0[kk].y, b0[kk].z, b0[kk].w,
                          b1[kk].x, b1[kk].y, b1[kk].z, b1[kk].w};
#pragma unroll
            for (int i = 0; i < 8; ++i) {
                float a = (kk == 0) ? a4[i].x : (kk == 1) ? a4[i].y
                         : (kk == 2) ? a4[i].z : a4[i].w;
#pragma unroll
                for (int j = 0; j < 8; ++j)
                    acc[i * 8 + j] = fmaf(a, b[j], acc[i * 8 + j]);
            }
        }
    }
}

__device__ __forceinline__ float sigmoidf_(float x) {
    return 1.0f / (1.0f + expf(-x));
}

// ---------------- the fused GNN kernel: one CTA per (b,s) ----------------
__global__ void __launch_bounds__(256, 1)
gnn_main(const int* __restrict__ input_var,
         const float* __restrict__ adj,
         const float* __restrict__ emb,
         const float* __restrict__ b_ih,
         const float* __restrict__ b_hh,
         const float* __restrict__ mb1,
         const float* __restrict__ mb2,
         const float* __restrict__ mW3,
         const float* __restrict__ mb3,
         float* __restrict__ out) {
    extern __shared__ float sm[];
    float* nf = sm;                       // [128][SST] node features (persistent)
    float* sb = nf + LDIM * SST;          // [128][SST] s = A@nf / h1
    float* Rb = sb + LDIM * SST;          // [128][SST] r -> n / h2
    unsigned* mask = (unsigned*)(Rb + LDIM * SST);  // [128][4] adjacency bitmask
    float* deg = (float*)(mask + LDIM * 4);         // [128] row degrees

    const int tid = threadIdx.x;
    const int tx = tid & 15, ty = tid >> 4;
    const int lane = tid & 31, warp = tid >> 5;
    const int bs = blockIdx.x;
    const int row0 = ty * 8, col0 = tx * 8;

    // ---- embedding gather: nf[l][:] = emb[input_var[bs][l]][:]
    {
        const int* iv = input_var + bs * LDIM;
        for (int r = 0; r < 16; ++r) {
            int l = warp * 16 + r;
            int idx = iv[l];
            float4 v = ((const float4*)(emb + (size_t)idx * HDIM))[lane];
            *(float4*)(nf + l * SST + lane * 4) = v;
        }
    }

    // ---- adjacency -> bitmask (each thread builds 2 of the 512 words)
    {
        const float4* ab = (const float4*)(adj + (size_t)bs * LDIM * LDIM);
#pragma unroll
        for (int ww = 0; ww < 2; ++ww) {
            int w = tid * 2 + ww;
            int l = w >> 2, part = w & 3;
            const float4* p = ab + (l * LDIM + part * 32) / 4;
            unsigned m = 0;
#pragma unroll
            for (int q = 0; q < 8; ++q) {
                float4 v = p[q];
                m |= (v.x > 0.5f ? 1u : 0u) << (q * 4 + 0);
                m |= (v.y > 0.5f ? 1u : 0u) << (q * 4 + 1);
                m |= (v.z > 0.5f ? 1u : 0u) << (q * 4 + 2);
                m |= (v.w > 0.5f ? 1u : 0u) << (q * 4 + 3);
            }
            mask[w] = m;
        }
    }
    __syncthreads();
    if (tid < LDIM) {
        deg[tid] = (float)(__popc(mask[tid * 4 + 0]) + __popc(mask[tid * 4 + 1]) +
                           __popc(mask[tid * 4 + 2]) + __popc(mask[tid * 4 + 3]));
    }
    __syncthreads();

    float acc[64], accB[64];

    // ---- 10 GRU iterations, fully in SMEM ----
    for (int it = 0; it < NUM_LOOP; ++it) {
        // s = A @ nf via bitmask gather (warp owns 16 rows; lane owns 4 h cols)
        for (int r = 0; r < 16; ++r) {
            int l = warp * 16 + r;
            float4 a = make_float4(0.f, 0.f, 0.f, 0.f);
#pragma unroll
            for (int w4 = 0; w4 < 4; ++w4) {
                unsigned m = mask[l * 4 + w4];
                while (m) {
                    int c = w4 * 32 + __ffs((int)m) - 1;
                    m &= m - 1;
                    float4 v = *(const float4*)(nf + c * SST + lane * 4);
                    a.x += v.x; a.y += v.y; a.z += v.z; a.w += v.w;
                }
            }
            *(float4*)(sb + l * SST + lane * 4) = a;
        }
        __syncthreads();

        // ---- R gate: r = sigmoid(s@G_r + deg*u_r + b_ih_r + nf@Whh_r + b_hh_r)
#pragma unroll
        for (int i = 0; i < 64; ++i) acc[i] = 0.f;
        gemm1(sb, g_Gt + 0, 384, acc, tx, ty);
        gemm1(nf, g_Whht + 0, 384, acc, tx, ty);
#pragma unroll
        for (int i = 0; i < 8; ++i) {
            int l = row0 + i;
            float dg = deg[l];
#pragma unroll
            for (int j = 0; j < 8; ++j) {
                int h = col0 + j;
                float v = acc[i * 8 + j] + dg * g_u[h] + b_ih[h] + b_hh[h];
                Rb[l * SST + h] = sigmoidf_(v);
            }
        }

        // ---- n gate: n = tanh( (s@G_n + deg*u_n + b_ih_n) + r * (nf@Whh_n + b_hh_n) )
#pragma unroll
        for (int i = 0; i < 64; ++i) { acc[i] = 0.f; accB[i] = 0.f; }
        gemm1(sb, g_Gt + 256, 384, acc, tx, ty);
        gemm1(nf, g_Whht + 256, 384, accB, tx, ty);
#pragma unroll
        for (int i = 0; i < 8; ++i) {
            int l = row0 + i;
            float dg = deg[l];
#pragma unroll
            for (int j = 0; j < 8; ++j) {
                int h = col0 + j;
                float ni = acc[i * 8 + j] + dg * g_u[256 + h] + b_ih[256 + h];
                float hn = accB[i * 8 + j] + b_hh[256 + h];
                float r = Rb[l * SST + h];          // same-thread coords: no race
                Rb[l * SST + h] = tanhf(ni + r * hn);  // overwrite r with n
            }
        }

        // ---- Z gate + state update: nf = n + z*(nf - n)
#pragma unroll
        for (int i = 0; i < 64; ++i) acc[i] = 0.f;
        gemm1(sb, g_Gt + 128, 384, acc, tx, ty);
        gemm1(nf, g_Whht + 128, 384, acc, tx, ty);
        __syncthreads();  // all reads of nf/sb complete before nf is overwritten
#pragma unroll
        for (int i = 0; i < 8; ++i) {
            int l = row0 + i;
            float dg = deg[l];
#pragma unroll
            for (int j = 0; j < 8; ++j) {
                int h = col0 + j;
                float v = acc[i * 8 + j] + dg * g_u[128 + h] + b_ih[128 + h] + b_hh[128 + h];
                float z = sigmoidf_(v);
                float n = Rb[l * SST + h];
                float old = nf[l * SST + h];
                nf[l * SST + h] = n + z * (old - n);
            }
        }
        __syncthreads();
    }

    // ---- mention MLP: h1 = tanh(nf@mW1^T+b1); h2 = tanh(h1@mW2^T+b2); tanh(h2@mW3^T+b3)
#pragma unroll
    for (int i = 0; i < 64; ++i) acc[i] = 0.f;
    gemm1(nf, g_m1t, 128, acc, tx, ty);
#pragma unroll
    for (int i = 0; i < 8; ++i)
#pragma unroll
        for (int j = 0; j < 8; ++j)
            sb[(row0 + i) * SST + col0 + j] = tanhf(acc[i * 8 + j] + mb1[col0 + j]);
    __syncthreads();

#pragma unroll
    for (int i = 0; i < 64; ++i) acc[i] = 0.f;
    gemm1(sb, g_m2t, 128, acc, tx, ty);
#pragma unroll
    for (int i = 0; i < 8; ++i)
#pragma unroll
        for (int j = 0; j < 8; ++j)
            Rb[(row0 + i) * SST + col0 + j] = tanhf(acc[i * 8 + j] + mb2[col0 + j]);
    __syncthreads();

    if (tid < LDIM) {
        float a = mb3[0];
#pragma unroll 4
        for (int h = 0; h < HDIM; ++h)
            a = fmaf(Rb[tid * SST + h], mW3[h], a);
        out[bs * LDIM + tid] = tanhf(a);
    }
}

// ---------------- launch ----------------
extern "C" void kernel_launch(void* const* d_in, const int* in_sizes, int n_in,
                              void* d_out, int out_size) {
    const int*   input_var = (const int*)  d_in[0];
    const float* adjacency = (const float*)d_in[1];
    const float* emb       = (const float*)d_in[2];
    const float* gnn_w     = (const float*)d_in[3];
    const float* gnn_b     = (const float*)d_in[4];
    const float* W_ih      = (const float*)d_in[5];
    const float* W_hh      = (const float*)d_in[6];
    const float* b_ih      = (const float*)d_in[7];
    const float* b_hh      = (const float*)d_in[8];
    const float* mW1       = (const float*)d_in[9];
    const float* mb1       = (const float*)d_in[10];
    const float* mW2       = (const float*)d_in[11];
    const float* mb2       = (const float*)d_in[12];
    const float* mW3       = (const float*)d_in[13];
    const float* mb3       = (const float*)d_in[14];
    float* out = (float*)d_out;

    // prep: fused weight products + transposes (deterministic, recomputed every call)
    prep_gemm<<<(128 * 384 + 255) / 256, 256>>>(gnn_w, W_ih, gnn_b);
    prep_trans<<<(128 * 384 + 2 * 128 * 128 + 255) / 256, 256>>>(W_hh, mW1, mW2);

    const int smem_bytes = (3 * LDIM * SST) * 4 + LDIM * 4 * 4 + LDIM * 4;
    cudaFuncSetAttribute(gnn_main, cudaFuncAttributeMaxDynamicSharedMemorySize, smem_bytes);
    gnn_main<<<NBS, 256, smem_bytes>>>(input_var, adjacency, emb,
                                       b_ih, b_hh, mb1, mb2, mW3, mb3, out);
}

// round 8
// speedup vs baseline: 1.0001x; 1.0001x over previous
#include <cuda_runtime.h>
#include <math.h>

// Problem constants (fixed by the dataset)
#define LDIM 128        // nodes per sentence
#define HDIM 128        // hidden
#define NBS  2048       // B*S sentences
#define SST  132        // smem row stride (pad to dodge conflicts)
#define NUM_LOOP 10

// ---------------- device scratch (no cudaMalloc allowed) ----------------
__device__ float g_Gt[128 * 384];    // (gnn_w @ W_ih^T), row-major [k][j]
__device__ float g_Whht[128 * 384];  // W_hh^T, [k][j] = W_hh[j][k]
__device__ float g_u[384];           // gnn_b @ W_ih^T
__device__ float g_m1t[128 * 128];   // mW1^T
__device__ float g_m2t[128 * 128];   // mW2^T

// ---------------- prep kernels (run every launch; deterministic) --------
__global__ void prep_gemm(const float* __restrict__ gnn_w,
                          const float* __restrict__ W_ih,
                          const float* __restrict__ gnn_b) {
    int t = blockIdx.x * blockDim.x + threadIdx.x;
    if (t < 128 * 384) {
        int k = t / 384, j = t % 384;
        const float* wr = gnn_w + k * 128;
        const float* ir = W_ih + j * 128;
        float acc = 0.f;
#pragma unroll 4
        for (int m = 0; m < 128; ++m) acc = fmaf(wr[m], ir[m], acc);
        g_Gt[t] = acc;
        if (t < 384) {
            const float* ir2 = W_ih + t * 128;
            float a2 = 0.f;
#pragma unroll 4
            for (int m = 0; m < 128; ++m) a2 = fmaf(gnn_b[m], ir2[m], a2);
            g_u[t] = a2;
        }
    }
}

__global__ void prep_trans(const float* __restrict__ W_hh,
                           const float* __restrict__ mW1,
                           const float* __restrict__ mW2) {
    int t = blockIdx.x * blockDim.x + threadIdx.x;
    if (t < 128 * 384) {
        int k = t / 384, j = t % 384;
        g_Whht[t] = W_hh[j * 128 + k];
    } else if (t < 128 * 384 + 128 * 128) {
        int q = t - 128 * 384;
        int k = q / 128, j = q % 128;
        g_m1t[q] = mW1[j * 128 + k];
    } else if (t < 128 * 384 + 2 * 128 * 128) {
        int q = t - 128 * 384 - 128 * 128;
        int k = q / 128, j = q % 128;
        g_m2t[q] = mW2[j * 128 + k];
    }
}

// ---------------- register-tiled GEMM: C[128,128] += A_smem[128,128] @ B_glb[128,ldb] ----
// Thread (tx,ty) in 16x16 grid owns 8x8 C tile: rows ty*8.., cols tx*8..
__device__ __forceinline__ void gemm1(const float* __restrict__ A,
                                      const float* __restrict__ B,
                                      int ldb,
                                      float* __restrict__ acc,
                                      int tx, int ty) {
    const float* Ar = A + ty * 8 * SST;
    const float* Bp = B + tx * 8;
#pragma unroll 2
    for (int k4 = 0; k4 < 128; k4 += 4) {
        float4 a4[8];
#pragma unroll
        for (int i = 0; i < 8; ++i)
            a4[i] = *(const float4*)(Ar + i * SST + k4);
        float4 b0[4], b1[4];
#pragma unroll
        for (int kk = 0; kk < 4; ++kk) {
            b0[kk] = *(const float4*)(Bp + (k4 + kk) * ldb);
            b1[kk] = *(const float4*)(Bp + (k4 + kk) * ldb + 4);
        }
#pragma unroll
        for (int kk = 0; kk < 4; ++kk) {
            float b[8] = {b0[kk].x, b0[kk].y, b0[kk].z, b0[kk].w,
                          b1[kk].x, b1[kk].y, b1[kk].z, b1[kk].w};
#pragma unroll
            for (int i = 0; i < 8; ++i) {
                float a = (kk == 0) ? a4[i].x : (kk == 1) ? a4[i].y
                         : (kk == 2) ? a4[i].z : a4[i].w;
#pragma unroll
                for (int j = 0; j < 8; ++j)
                    acc[i * 8 + j] = fmaf(a, b[j], acc[i * 8 + j]);
            }
        }
    }
}

__device__ __forceinline__ float sigmoidf_(float x) {
    return 1.0f / (1.0f + expf(-x));
}

// ---------------- the fused GNN kernel: one CTA per (b,s) ----------------
__global__ void __launch_bounds__(256, 1)
gnn_main(const int* __restrict__ input_var,
         const float* __restrict__ adj,
         const float* __restrict__ emb,
         const float* __restrict__ b_ih,
         const float* __restrict__ b_hh,
         const float* __restrict__ mb1,
         const float* __restrict__ mb2,
         const float* __restrict__ mW3,
         const float* __restrict__ mb3,
         float* __restrict__ out) {
    extern __shared__ float sm[];
    float* nf = sm;                       // [128][SST] node features (persistent)
    float* sb = nf + LDIM * SST;          // [128][SST] s = A@nf / h1
    float* Rb = sb + LDIM * SST;          // [128][SST] r -> n / h2
    unsigned* mask = (unsigned*)(Rb + LDIM * SST);  // [128][4] adjacency bitmask
    float* deg = (float*)(mask + LDIM * 4);         // [128] row degrees

    const int tid = threadIdx.x;
    const int tx = tid & 15, ty = tid >> 4;
    const int lane = tid & 31, warp = tid >> 5;
    const int bs = blockIdx.x;
    const int row0 = ty * 8, col0 = tx * 8;

    // ---- embedding gather: nf[l][:] = emb[input_var[bs][l]][:]
    {
        const int* iv = input_var + bs * LDIM;
        for (int r = 0; r < 16; ++r) {
            int l = warp * 16 + r;
            int idx = iv[l];
            float4 v = ((const float4*)(emb + (size_t)idx * HDIM))[lane];
            *(float4*)(nf + l * SST + lane * 4) = v;
        }
    }

    // ---- adjacency -> bitmask (each thread builds 2 of the 512 words)
    {
        const float4* ab = (const float4*)(adj + (size_t)bs * LDIM * LDIM);
#pragma unroll
        for (int ww = 0; ww < 2; ++ww) {
            int w = tid * 2 + ww;
            int l = w >> 2, part = w & 3;
            const float4* p = ab + (l * LDIM + part * 32) / 4;
            unsigned m = 0;
#pragma unroll
            for (int q = 0; q < 8; ++q) {
                float4 v = p[q];
                m |= (v.x > 0.5f ? 1u : 0u) << (q * 4 + 0);
                m |= (v.y > 0.5f ? 1u : 0u) << (q * 4 + 1);
                m |= (v.z > 0.5f ? 1u : 0u) << (q * 4 + 2);
                m |= (v.w > 0.5f ? 1u : 0u) << (q * 4 + 3);
            }
            mask[w] = m;
        }
    }
    __syncthreads();
    if (tid < LDIM) {
        deg[tid] = (float)(__popc(mask[tid * 4 + 0]) + __popc(mask[tid * 4 + 1]) +
                           __popc(mask[tid * 4 + 2]) + __popc(mask[tid * 4 + 3]));
    }
    __syncthreads();

    float acc[64], accB[64];

    // ---- 10 GRU iterations, fully in SMEM ----
    for (int it = 0; it < NUM_LOOP; ++it) {
        // s = A @ nf via bitmask gather (warp owns 16 rows; lane owns 4 h cols)
        for (int r = 0; r < 16; ++r) {
            int l = warp * 16 + r;
            float4 a = make_float4(0.f, 0.f, 0.f, 0.f);
#pragma unroll
            for (int w4 = 0; w4 < 4; ++w4) {
                unsigned m = mask[l * 4 + w4];
                while (m) {
                    int c = w4 * 32 + __ffs((int)m) - 1;
                    m &= m - 1;
                    float4 v = *(const float4*)(nf + c * SST + lane * 4);
                    a.x += v.x; a.y += v.y; a.z += v.z; a.w += v.w;
                }
            }
            *(float4*)(sb + l * SST + lane * 4) = a;
        }
        __syncthreads();

        // ---- R gate: r = sigmoid(s@G_r + deg*u_r + b_ih_r + nf@Whh_r + b_hh_r)
#pragma unroll
        for (int i = 0; i < 64; ++i) acc[i] = 0.f;
        gemm1(sb, g_Gt + 0, 384, acc, tx, ty);
        gemm1(nf, g_Whht + 0, 384, acc, tx, ty);
#pragma unroll
        for (int i = 0; i < 8; ++i) {
            int l = row0 + i;
            float dg = deg[l];
#pragma unroll
            for (int j = 0; j < 8; ++j) {
                int h = col0 + j;
                float v = acc[i * 8 + j] + dg * g_u[h] + b_ih[h] + b_hh[h];
                Rb[l * SST + h] = sigmoidf_(v);
            }
        }

        // ---- n gate: n = tanh( (s@G_n + deg*u_n + b_ih_n) + r * (nf@Whh_n + b_hh_n) )
#pragma unroll
        for (int i = 0; i < 64; ++i) { acc[i] = 0.f; accB[i] = 0.f; }
        gemm1(sb, g_Gt + 256, 384, acc, tx, ty);
        gemm1(nf, g_Whht + 256, 384, accB, tx, ty);
#pragma unroll
        for (int i = 0; i < 8; ++i) {
            int l = row0 + i;
            float dg = deg[l];
#pragma unroll
            for (int j = 0; j < 8; ++j) {
                int h = col0 + j;
                float ni = acc[i * 8 + j] + dg * g_u[256 + h] + b_ih[256 + h];
                float hn = accB[i * 8 + j] + b_hh[256 + h];
                float r = Rb[l * SST + h];          // same-thread coords: no race
                Rb[l * SST + h] = tanhf(ni + r * hn);  // overwrite r with n
            }
        }

        // ---- Z gate + state update: nf = n + z*(nf - n)
#pragma unroll
        for (int i = 0; i < 64; ++i) acc[i] = 0.f;
        gemm1(sb, g_Gt + 128, 384, acc, tx, ty);
        gemm1(nf, g_Whht + 128, 384, acc, tx, ty);
        __syncthreads();  // all reads of nf/sb complete before nf is overwritten
#pragma unroll
        for (int i = 0; i < 8; ++i) {
            int l = row0 + i;
            float dg = deg[l];
#pragma unroll
            for (int j = 0; j < 8; ++j) {
                int h = col0 + j;
                float v = acc[i * 8 + j] + dg * g_u[128 + h] + b_ih[128 + h] + b_hh[128 + h];
                float z = sigmoidf_(v);
                float n = Rb[l * SST + h];
                float old = nf[l * SST + h];
                nf[l * SST + h] = n + z * (old - n);
            }
        }
        __syncthreads();
    }

    // ---- mention MLP: h1 = tanh(nf@mW1^T+b1); h2 = tanh(h1@mW2^T+b2); tanh(h2@mW3^T+b3)
#pragma unroll
    for (int i = 0; i < 64; ++i) acc[i] = 0.f;
    gemm1(nf, g_m1t, 128, acc, tx, ty);
#pragma unroll
    for (int i = 0; i < 8; ++i)
#pragma unroll
        for (int j = 0; j < 8; ++j)
            sb[(row0 + i) * SST + col0 + j] = tanhf(acc[i * 8 + j] + mb1[col0 + j]);
    __syncthreads();

#pragma unroll
    for (int i = 0; i < 64; ++i) acc[i] = 0.f;
    gemm1(sb, g_m2t, 128, acc, tx, ty);
#pragma unroll
    for (int i = 0; i < 8; ++i)
#pragma unroll
        for (int j = 0; j < 8; ++j)
            Rb[(row0 + i) * SST + col0 + j] = tanhf(acc[i * 8 + j] + mb2[col0 + j]);
    __syncthreads();

    if (tid < LDIM) {
        float a = mb3[0];
#pragma unroll 4
        for (int h = 0; h < HDIM; ++h)
            a = fmaf(Rb[tid * SST + h], mW3[h], a);
        out[bs * LDIM + tid] = tanhf(a);
    }
}

// ---------------- launch ----------------
extern "C" void kernel_launch(void* const* d_in, const int* in_sizes, int n_in,
                              void* d_out, int out_size) {
    const int*   input_var = (const int*)  d_in[0];
    const float* adjacency = (const float*)d_in[1];
    const float* emb       = (const float*)d_in[2];
    const float* gnn_w     = (const float*)d_in[3];
    const float* gnn_b     = (const float*)d_in[4];
    const float* W_ih      = (const float*)d_in[5];
    const float* W_hh      = (const float*)d_in[6];
    const float* b_ih      = (const float*)d_in[7];
    const float* b_hh      = (const float*)d_in[8];
    const float* mW1       = (const float*)d_in[9];
    const float* mb1       = (const float*)d_in[10];
    const float* mW2       = (const float*)d_in[11];
    const float* mb2       = (const float*)d_in[12];
    const float* mW3       = (const float*)d_in[13];
    const float* mb3       = (const float*)d_in[14];
    float* out = (float*)d_out;

    // prep: fused weight products + transposes (deterministic, recomputed every call)
    prep_gemm<<<(128 * 384 + 255) / 256, 256>>>(gnn_w, W_ih, gnn_b);
    prep_trans<<<(128 * 384 + 2 * 128 * 128 + 255) / 256, 256>>>(W_hh, mW1, mW2);

    const int smem_bytes = (3 * LDIM * SST) * 4 + LDIM * 4 * 4 + LDIM * 4;
    cudaFuncSetAttribute(gnn_main, cudaFuncAttributeMaxDynamicSharedMemorySize, smem_bytes);
    gnn_main<<<NBS, 256, smem_bytes>>>(input_var, adjacency, emb,
                                       b_ih, b_hh, mb1, mb2, mW3, mb3, out);
}

// round 10
// speedup vs baseline: 1.3000x; 1.2999x over previous
#include <cuda_runtime.h>
#include <math.h>

// Problem constants (fixed by the dataset)
#define LDIM 128        // nodes per sentence
#define HDIM 128        // hidden
#define NBS  2048       // B*S sentences
#define SST  132        // smem row stride for activations (row step 528B = 16 mod 128 -> conflict-free)
#define NUM_LOOP 10

// ---------------- device scratch (no cudaMalloc allowed) ----------------
__device__ float g_Gt[128 * 384];    // (gnn_w @ W_ih^T), row-major [k][j]
__device__ float g_Whht[128 * 384];  // W_hh^T, [k][j] = W_hh[j][k]
__device__ float g_u[384];           // gnn_b @ W_ih^T
__device__ float g_m1t[128 * 128];   // mW1^T
__device__ float g_m2t[128 * 128];   // mW2^T

// ---------------- prep kernels (run every launch; deterministic) --------
__global__ void prep_gemm(const float* __restrict__ gnn_w,
                          const float* __restrict__ W_ih,
                          const float* __restrict__ gnn_b) {
    int t = blockIdx.x * blockDim.x + threadIdx.x;
    if (t < 128 * 384) {
        int k = t / 384, j = t % 384;
        const float* wr = gnn_w + k * 128;
        const float* ir = W_ih + j * 128;
        float acc = 0.f;
#pragma unroll 4
        for (int m = 0; m < 128; ++m) acc = fmaf(wr[m], ir[m], acc);
        g_Gt[t] = acc;
        if (t < 384) {
            const float* ir2 = W_ih + t * 128;
            float a2 = 0.f;
#pragma unroll 4
            for (int m = 0; m < 128; ++m) a2 = fmaf(gnn_b[m], ir2[m], a2);
            g_u[t] = a2;
        }
    }
}

__global__ void prep_trans(const float* __restrict__ W_hh,
                           const float* __restrict__ mW1,
                           const float* __restrict__ mW2) {
    int t = blockIdx.x * blockDim.x + threadIdx.x;
    if (t < 128 * 384) {
        int k = t / 384, j = t % 384;
        g_Whht[t] = W_hh[j * 128 + k];
    } else if (t < 128 * 384 + 128 * 128) {
        int q = t - 128 * 384;
        int k = q / 128, j = q % 128;
        g_m1t[q] = mW1[j * 128 + k];
    } else if (t < 128 * 384 + 2 * 128 * 128) {
        int q = t - 128 * 384 - 128 * 128;
        int k = q / 128, j = q % 128;
        g_m2t[q] = mW2[j * 128 + k];
    }
}

// ---------------- packed f32x2 helpers ----------------
__device__ __forceinline__ float2 unpk(unsigned long long v) {
    float2 r;
    asm("mov.b64 {%0, %1}, %2;" : "=f"(r.x), "=f"(r.y) : "l"(v));
    return r;
}
__device__ __forceinline__ unsigned long long pk(float x, float y) {
    unsigned long long v;
    asm("mov.b64 %0, {%1, %2};" : "=l"(v) : "f"(x), "f"(y));
    return v;
}

// fast, accurate-enough activations (error ~1e-6; budget is 1e-3)
__device__ __forceinline__ float fsig(float x) {
    float e = __expf(-x);
    return __fdividef(1.0f, 1.0f + e);
}
__device__ __forceinline__ float ftanh(float x) {
    float e = __expf(2.0f * x);          // inf for large x -> 1; 0 for very neg -> -1
    return 1.0f - __fdividef(2.0f, e + 1.0f);
}

// ---------------- stage a 128x128 weight chunk: global -> SMEM ----------------
// FIXED: full tile is 4096 float4 (128 rows x 32 float4/row); 256 threads -> 16 iters.
__device__ __forceinline__ void stageB(const float* __restrict__ src, int ld, int coloff,
                                       float* __restrict__ Bs, int tid) {
#pragma unroll
    for (int q = 0; q < 16; ++q) {
        int idx = q * 256 + tid;      // 0..4095
        int row = idx >> 5;           // 32 float4 per row
        int c4  = idx & 31;
        *(float4*)(Bs + row * 128 + c4 * 4) =
            *(const float4*)(src + row * ld + coloff + c4 * 4);
    }
}

// ---------------- FFMA2 register-tiled GEMM: C[128,128] += A_smem @ Bs_smem ----
// Thread owns rows {r0 + 8*i, i=0..7} x cols [c0, c0+8). acc2[i*4+j2] packs cols (c0+2j2, c0+2j2+1).
__device__ __forceinline__ void gemm2(const float* __restrict__ A,
                                      const float* __restrict__ Bs,
                                      unsigned long long* __restrict__ acc2,
                                      int r0, int c0) {
    const float* Ar = A + r0 * SST;
    const float* Bp = Bs + c0;
#pragma unroll 1
    for (int k4 = 0; k4 < 128; k4 += 4) {
        float4 a4[8];
#pragma unroll
        for (int i = 0; i < 8; ++i)
            a4[i] = *(const float4*)(Ar + i * 8 * SST + k4);
#pragma unroll
        for (int kk = 0; kk < 4; ++kk) {
            ulonglong2 bA = *(const ulonglong2*)(Bp + (k4 + kk) * 128);
            ulonglong2 bB = *(const ulonglong2*)(Bp + (k4 + kk) * 128 + 4);
            unsigned long long bb0 = bA.x, bb1 = bA.y, bb2 = bB.x, bb3 = bB.y;
#pragma unroll
            for (int i = 0; i < 8; ++i) {
                float a = (kk == 0) ? a4[i].x : (kk == 1) ? a4[i].y
                         : (kk == 2) ? a4[i].z : a4[i].w;
                unsigned int au = __float_as_uint(a);
                unsigned long long aa;
                asm("mov.b64 %0, {%1, %1};" : "=l"(aa) : "r"(au));
                asm("fma.rn.f32x2 %0, %1, %2, %0;" : "+l"(acc2[i * 4 + 0]) : "l"(aa), "l"(bb0));
                asm("fma.rn.f32x2 %0, %1, %2, %0;" : "+l"(acc2[i * 4 + 1]) : "l"(aa), "l"(bb1));
                asm("fma.rn.f32x2 %0, %1, %2, %0;" : "+l"(acc2[i * 4 + 2]) : "l"(aa), "l"(bb2));
                asm("fma.rn.f32x2 %0, %1, %2, %0;" : "+l"(acc2[i * 4 + 3]) : "l"(aa), "l"(bb3));
            }
        }
    }
}

// ---------------- the fused GNN kernel: one CTA per (b,s) ----------------
__global__ void __launch_bounds__(256, 1)
gnn_main(const int* __restrict__ input_var,
         const float* __restrict__ adj,
         const float* __restrict__ emb,
         const float* __restrict__ b_ih,
         const float* __restrict__ b_hh,
         const float* __restrict__ mb1,
         const float* __restrict__ mb2,
         const float* __restrict__ mW3,
         const float* __restrict__ mb3,
         float* __restrict__ out) {
    extern __shared__ float sm[];
    float* nf = sm;                        // [128][SST] node features (persistent)
    float* sb = nf + LDIM * SST;           // [128][SST] s = A@nf  (later h1)
    float* Bs = sb + LDIM * SST;           // [128][128] staged weight chunk
    unsigned* mask = (unsigned*)(Bs + 128 * 128);   // [128][4] adjacency bitmask
    float* deg  = (float*)(mask + LDIM * 4);        // [128]
    float* su   = deg + LDIM;              // [384]  gnn_b @ W_ih^T
    float* sbih = su + 384;                // [384]
    float* sbhh = sbih + 384;              // [384]
    float* smb1 = sbhh + 384;              // [128]
    float* smb2 = smb1 + 128;              // [128]

    const int tid = threadIdx.x;
    const int lane = tid & 31, warp = tid >> 5;
    const int lr = lane & 7, lc = lane >> 3;     // 8 x 4 lanes
    const int wr = warp & 1, wc = warp >> 1;     // 2 x 4 warps
    const int r0 = wr * 64 + lr;                 // rows: r0 + 8*i
    const int c0 = (wc * 4 + lc) * 8;            // cols: c0 .. c0+7
    const int bs_idx = blockIdx.x;

    // ---- stage small vectors ----
    for (int t = tid; t < 384; t += 256) {
        su[t] = g_u[t]; sbih[t] = b_ih[t]; sbhh[t] = b_hh[t];
    }
    if (tid < 128) { smb1[tid] = mb1[tid]; smb2[tid] = mb2[tid]; }

    // ---- embedding gather: nf[l][:] = emb[input_var[bs][l]][:]
    {
        const int* iv = input_var + bs_idx * LDIM;
        for (int r = 0; r < 16; ++r) {
            int l = warp * 16 + r;
            int idx = iv[l];
            float4 v = ((const float4*)(emb + (size_t)idx * HDIM))[lane];
            *(float4*)(nf + l * SST + lane * 4) = v;
        }
    }

    // ---- adjacency -> bitmask (each thread builds 2 of the 512 words)
    {
        const float4* ab = (const float4*)(adj + (size_t)bs_idx * LDIM * LDIM);
#pragma unroll
        for (int ww = 0; ww < 2; ++ww) {
            int w = tid * 2 + ww;
            int l = w >> 2, part = w & 3;
            const float4* p = ab + (l * LDIM + part * 32) / 4;
            unsigned m = 0;
#pragma unroll
            for (int q = 0; q < 8; ++q) {
                float4 v = p[q];
                m |= (v.x > 0.5f ? 1u : 0u) << (q * 4 + 0);
                m |= (v.y > 0.5f ? 1u : 0u) << (q * 4 + 1);
                m |= (v.z > 0.5f ? 1u : 0u) << (q * 4 + 2);
                m |= (v.w > 0.5f ? 1u : 0u) << (q * 4 + 3);
            }
            mask[w] = m;
        }
    }
    __syncthreads();
    if (tid < LDIM) {
        deg[tid] = (float)(__popc(mask[tid * 4 + 0]) + __popc(mask[tid * 4 + 1]) +
                           __popc(mask[tid * 4 + 2]) + __popc(mask[tid * 4 + 3]));
    }
    __syncthreads();

    unsigned long long acc2[32];
    float rn[64];   // holds r during n-phase, then n during z-phase

    // ---- 10 GRU iterations, fully in SMEM ----
    for (int it = 0; it < NUM_LOOP; ++it) {
        // s = A @ nf via bitmask gather (warp owns 16 rows; lane owns 4 h cols)
        for (int r = 0; r < 16; ++r) {
            int l = warp * 16 + r;
            float4 a = make_float4(0.f, 0.f, 0.f, 0.f);
#pragma unroll
            for (int w4 = 0; w4 < 4; ++w4) {
                unsigned m = mask[l * 4 + w4];
                while (m) {
                    int c = w4 * 32 + __ffs((int)m) - 1;
                    m &= m - 1;
                    float4 v = *(const float4*)(nf + c * SST + lane * 4);
                    a.x += v.x; a.y += v.y; a.z += v.z; a.w += v.w;
                }
            }
            *(float4*)(sb + l * SST + lane * 4) = a;
        }
        stageB(g_Gt, 384, 0, Bs, tid);        // G_r (overlaps with gather)
        __syncthreads();

        // ================= R gate: r = sigmoid(s@G_r + nf@Whh_r + deg*u_r + b) ======
#pragma unroll
        for (int p = 0; p < 32; ++p) acc2[p] = 0ull;
        gemm2(sb, Bs, acc2, r0, c0);
        __syncthreads();
        stageB(g_Whht, 384, 0, Bs, tid);      // Whh_r
        __syncthreads();
        gemm2(nf, Bs, acc2, r0, c0);
#pragma unroll
        for (int i = 0; i < 8; ++i) {
            int row = r0 + i * 8;
            float dg = deg[row];
#pragma unroll
            for (int j2 = 0; j2 < 4; ++j2) {
                int h = c0 + j2 * 2;
                float2 v = unpk(acc2[i * 4 + j2]);
                rn[i * 8 + j2 * 2 + 0] = fsig(v.x + dg * su[h]     + sbih[h]     + sbhh[h]);
                rn[i * 8 + j2 * 2 + 1] = fsig(v.y + dg * su[h + 1] + sbih[h + 1] + sbhh[h + 1]);
            }
        }

        // ================= n gate: n = tanh(s@G_n + deg*u_n + b_ih_n + r*(nf@Whh_n + b_hh_n))
        __syncthreads();
        stageB(g_Whht, 384, 256, Bs, tid);    // Whh_n
        __syncthreads();
#pragma unroll
        for (int p = 0; p < 32; ++p) acc2[p] = 0ull;
        gemm2(nf, Bs, acc2, r0, c0);
#pragma unroll
        for (int i = 0; i < 8; ++i) {
#pragma unroll
            for (int j2 = 0; j2 < 4; ++j2) {
                int h = c0 + j2 * 2;
                float2 v = unpk(acc2[i * 4 + j2]);
                v.x = rn[i * 8 + j2 * 2 + 0] * (v.x + sbhh[256 + h]);
                v.y = rn[i * 8 + j2 * 2 + 1] * (v.y + sbhh[256 + h + 1]);
                acc2[i * 4 + j2] = pk(v.x, v.y);
            }
        }
        __syncthreads();
        stageB(g_Gt, 384, 256, Bs, tid);      // G_n
        __syncthreads();
        gemm2(sb, Bs, acc2, r0, c0);
#pragma unroll
        for (int i = 0; i < 8; ++i) {
            int row = r0 + i * 8;
            float dg = deg[row];
#pragma unroll
            for (int j2 = 0; j2 < 4; ++j2) {
                int h = c0 + j2 * 2;
                float2 v = unpk(acc2[i * 4 + j2]);
                rn[i * 8 + j2 * 2 + 0] = ftanh(v.x + dg * su[256 + h]     + sbih[256 + h]);
                rn[i * 8 + j2 * 2 + 1] = ftanh(v.y + dg * su[256 + h + 1] + sbih[256 + h + 1]);
            }
        }

        // ================= Z gate + state update: nf = n + z*(nf - n) ================
        __syncthreads();
        stageB(g_Gt, 384, 128, Bs, tid);      // G_z
        __syncthreads();
#pragma unroll
        for (int p = 0; p < 32; ++p) acc2[p] = 0ull;
        gemm2(sb, Bs, acc2, r0, c0);
        __syncthreads();
        stageB(g_Whht, 384, 128, Bs, tid);    // Whh_z
        __syncthreads();
        gemm2(nf, Bs, acc2, r0, c0);
        __syncthreads();   // all gemm reads of nf complete before any write
#pragma unroll
        for (int i = 0; i < 8; ++i) {
            int row = r0 + i * 8;
            float dg = deg[row];
#pragma unroll
            for (int j2 = 0; j2 < 4; ++j2) {
                int h = c0 + j2 * 2;
                float2 v = unpk(acc2[i * 4 + j2]);
                float zx = fsig(v.x + dg * su[128 + h]     + sbih[128 + h]     + sbhh[128 + h]);
                float zy = fsig(v.y + dg * su[128 + h + 1] + sbih[128 + h + 1] + sbhh[128 + h + 1]);
                float2 old = *(const float2*)(nf + row * SST + h);
                float nx = rn[i * 8 + j2 * 2 + 0];
                float ny = rn[i * 8 + j2 * 2 + 1];
                float2 nw;
                nw.x = nx + zx * (old.x - nx);
                nw.y = ny + zy * (old.y - ny);
                *(float2*)(nf + row * SST + h) = nw;
            }
        }
        __syncthreads();   // nf ready for next gather
    }

    // ---- mention MLP ----
    stageB(g_m1t, 128, 0, Bs, tid);
    __syncthreads();
#pragma unroll
    for (int p = 0; p < 32; ++p) acc2[p] = 0ull;
    gemm2(nf, Bs, acc2, r0, c0);
#pragma unroll
    for (int i = 0; i < 8; ++i) {
        int row = r0 + i * 8;
#pragma unroll
        for (int j2 = 0; j2 < 4; ++j2) {
            int h = c0 + j2 * 2;
            float2 v = unpk(acc2[i * 4 + j2]);
            float2 o;
            o.x = ftanh(v.x + smb1[h]);
            o.y = ftanh(v.y + smb1[h + 1]);
            *(float2*)(sb + row * SST + h) = o;
        }
    }
    __syncthreads();
    stageB(g_m2t, 128, 0, Bs, tid);
    __syncthreads();
#pragma unroll
    for (int p = 0; p < 32; ++p) acc2[p] = 0ull;
    gemm2(sb, Bs, acc2, r0, c0);
#pragma unroll
    for (int i = 0; i < 8; ++i) {
        int row = r0 + i * 8;
#pragma unroll
        for (int j2 = 0; j2 < 4; ++j2) {
            int h = c0 + j2 * 2;
            float2 v = unpk(acc2[i * 4 + j2]);
            float2 o;
            o.x = ftanh(v.x + smb2[h]);
            o.y = ftanh(v.y + smb2[h + 1]);
            *(float2*)(nf + row * SST + h) = o;   // h2 into nf (no longer needed)
        }
    }
    __syncthreads();

    if (tid < LDIM) {
        float a = mb3[0];
#pragma unroll 4
        for (int h = 0; h < HDIM; ++h)
            a = fmaf(nf[tid * SST + h], mW3[h], a);
        out[bs_idx * LDIM + tid] = ftanh(a);
    }
}

// ---------------- launch ----------------
extern "C" void kernel_launch(void* const* d_in, const int* in_sizes, int n_in,
                              void* d_out, int out_size) {
    const int*   input_var = (const int*)  d_in[0];
    const float* adjacency = (const float*)d_in[1];
    const float* emb       = (const float*)d_in[2];
    const float* gnn_w     = (const float*)d_in[3];
    const float* gnn_b     = (const float*)d_in[4];
    const float* W_ih      = (const float*)d_in[5];
    const float* W_hh      = (const float*)d_in[6];
    const float* b_ih      = (const float*)d_in[7];
    const float* b_hh      = (const float*)d_in[8];
    const float* mW1       = (const float*)d_in[9];
    const float* mb1       = (const float*)d_in[10];
    const float* mW2       = (const float*)d_in[11];
    const float* mb2       = (const float*)d_in[12];
    const float* mW3       = (const float*)d_in[13];
    const float* mb3       = (const float*)d_in[14];
    float* out = (float*)d_out;

    prep_gemm<<<(128 * 384 + 255) / 256, 256>>>(gnn_w, W_ih, gnn_b);
    prep_trans<<<(128 * 384 + 2 * 128 * 128 + 255) / 256, 256>>>(W_hh, mW1, mW2);

    // smem: nf + sb (128*132 each) + Bs (128*128) + mask(512 u32) + deg(128) + vectors(1408)
    const int smem_floats = 2 * LDIM * SST + 128 * 128 + 512 + 128 + 384 * 3 + 256;
    const int smem_bytes = smem_floats * 4;
    cudaFuncSetAttribute(gnn_main, cudaFuncAttributeMaxDynamicSharedMemorySize, smem_bytes);
    gnn_main<<<NBS, 256, smem_bytes>>>(input_var, adjacency, emb,
                                       b_ih, b_hh, mb1, mb2, mW3, mb3, out);
}

// round 11
// speedup vs baseline: 1.3011x; 1.0008x over previous
#include <cuda_runtime.h>
#include <math.h>

// Problem constants (fixed by the dataset)
#define LDIM 128        // nodes per sentence
#define HDIM 128        // hidden
#define NBS  2048       // B*S sentences
#define SST  132        // smem row stride for activations (row step 528B = 16 mod 128 -> conflict-free)
#define NUM_LOOP 10

// ---------------- device scratch (no cudaMalloc allowed) ----------------
__device__ float g_Gt[128 * 384];    // (gnn_w @ W_ih^T), row-major [k][j]
__device__ float g_Whht[128 * 384];  // W_hh^T, [k][j] = W_hh[j][k]
__device__ float g_u[384];           // gnn_b @ W_ih^T
__device__ float g_m1t[128 * 128];   // mW1^T
__device__ float g_m2t[128 * 128];   // mW2^T

// ---------------- prep kernels (run every launch; deterministic) --------
__global__ void prep_gemm(const float* __restrict__ gnn_w,
                          const float* __restrict__ W_ih,
                          const float* __restrict__ gnn_b) {
    int t = blockIdx.x * blockDim.x + threadIdx.x;
    if (t < 128 * 384) {
        int k = t / 384, j = t % 384;
        const float* wr = gnn_w + k * 128;
        const float* ir = W_ih + j * 128;
        float acc = 0.f;
#pragma unroll 4
        for (int m = 0; m < 128; ++m) acc = fmaf(wr[m], ir[m], acc);
        g_Gt[t] = acc;
        if (t < 384) {
            const float* ir2 = W_ih + t * 128;
            float a2 = 0.f;
#pragma unroll 4
            for (int m = 0; m < 128; ++m) a2 = fmaf(gnn_b[m], ir2[m], a2);
            g_u[t] = a2;
        }
    }
}

__global__ void prep_trans(const float* __restrict__ W_hh,
                           const float* __restrict__ mW1,
                           const float* __restrict__ mW2) {
    int t = blockIdx.x * blockDim.x + threadIdx.x;
    if (t < 128 * 384) {
        int k = t / 384, j = t % 384;
        g_Whht[t] = W_hh[j * 128 + k];
    } else if (t < 128 * 384 + 128 * 128) {
        int q = t - 128 * 384;
        int k = q / 128, j = q % 128;
        g_m1t[q] = mW1[j * 128 + k];
    } else if (t < 128 * 384 + 2 * 128 * 128) {
        int q = t - 128 * 384 - 128 * 128;
        int k = q / 128, j = q % 128;
        g_m2t[q] = mW2[j * 128 + k];
    }
}

// ---------------- packed f32x2 helpers ----------------
__device__ __forceinline__ float2 unpk(unsigned long long v) {
    float2 r;
    asm("mov.b64 {%0, %1}, %2;" : "=f"(r.x), "=f"(r.y) : "l"(v));
    return r;
}
__device__ __forceinline__ unsigned long long pk(float x, float y) {
    unsigned long long v;
    asm("mov.b64 %0, {%1, %2};" : "=l"(v) : "f"(x), "f"(y));
    return v;
}

// fast, accurate-enough activations (error ~1e-6; budget is 1e-3)
__device__ __forceinline__ float fsig(float x) {
    float e = __expf(-x);
    return __fdividef(1.0f, 1.0f + e);
}
__device__ __forceinline__ float ftanh(float x) {
    float e = __expf(2.0f * x);          // inf for large x -> 1; 0 for very neg -> -1
    return 1.0f - __fdividef(2.0f, e + 1.0f);
}

// ---------------- stage a 128x128 weight chunk: global -> SMEM ----------------
// FIXED: full tile is 4096 float4 (128 rows x 32 float4/row); 256 threads -> 16 iters.
__device__ __forceinline__ void stageB(const float* __restrict__ src, int ld, int coloff,
                                       float* __restrict__ Bs, int tid) {
#pragma unroll
    for (int q = 0; q < 16; ++q) {
        int idx = q * 256 + tid;      // 0..4095
        int row = idx >> 5;           // 32 float4 per row
        int c4  = idx & 31;
        *(float4*)(Bs + row * 128 + c4 * 4) =
            *(const float4*)(src + row * ld + coloff + c4 * 4);
    }
}

// ---------------- FFMA2 register-tiled GEMM: C[128,128] += A_smem @ Bs_smem ----
// Thread owns rows {r0 + 8*i, i=0..7} x cols [c0, c0+8). acc2[i*4+j2] packs cols (c0+2j2, c0+2j2+1).
__device__ __forceinline__ void gemm2(const float* __restrict__ A,
                                      const float* __restrict__ Bs,
                                      unsigned long long* __restrict__ acc2,
                                      int r0, int c0) {
    const float* Ar = A + r0 * SST;
    const float* Bp = Bs + c0;
#pragma unroll 1
    for (int k4 = 0; k4 < 128; k4 += 4) {
        float4 a4[8];
#pragma unroll
        for (int i = 0; i < 8; ++i)
            a4[i] = *(const float4*)(Ar + i * 8 * SST + k4);
#pragma unroll
        for (int kk = 0; kk < 4; ++kk) {
            ulonglong2 bA = *(const ulonglong2*)(Bp + (k4 + kk) * 128);
            ulonglong2 bB = *(const ulonglong2*)(Bp + (k4 + kk) * 128 + 4);
            unsigned long long bb0 = bA.x, bb1 = bA.y, bb2 = bB.x, bb3 = bB.y;
#pragma unroll
            for (int i = 0; i < 8; ++i) {
                float a = (kk == 0) ? a4[i].x : (kk == 1) ? a4[i].y
                         : (kk == 2) ? a4[i].z : a4[i].w;
                unsigned int au = __float_as_uint(a);
                unsigned long long aa;
                asm("mov.b64 %0, {%1, %1};" : "=l"(aa) : "r"(au));
                asm("fma.rn.f32x2 %0, %1, %2, %0;" : "+l"(acc2[i * 4 + 0]) : "l"(aa), "l"(bb0));
                asm("fma.rn.f32x2 %0, %1, %2, %0;" : "+l"(acc2[i * 4 + 1]) : "l"(aa), "l"(bb1));
                asm("fma.rn.f32x2 %0, %1, %2, %0;" : "+l"(acc2[i * 4 + 2]) : "l"(aa), "l"(bb2));
                asm("fma.rn.f32x2 %0, %1, %2, %0;" : "+l"(acc2[i * 4 + 3]) : "l"(aa), "l"(bb3));
            }
        }
    }
}

// ---------------- the fused GNN kernel: one CTA per (b,s) ----------------
__global__ void __launch_bounds__(256, 1)
gnn_main(const int* __restrict__ input_var,
         const float* __restrict__ adj,
         const float* __restrict__ emb,
         const float* __restrict__ b_ih,
         const float* __restrict__ b_hh,
         const float* __restrict__ mb1,
         const float* __restrict__ mb2,
         const float* __restrict__ mW3,
         const float* __restrict__ mb3,
         float* __restrict__ out) {
    extern __shared__ float sm[];
    float* nf = sm;                        // [128][SST] node features (persistent)
    float* sb = nf + LDIM * SST;           // [128][SST] s = A@nf  (later h1)
    float* Bs = sb + LDIM * SST;           // [128][128] staged weight chunk
    unsigned* mask = (unsigned*)(Bs + 128 * 128);   // [128][4] adjacency bitmask
    float* deg  = (float*)(mask + LDIM * 4);        // [128]
    float* su   = deg + LDIM;              // [384]  gnn_b @ W_ih^T
    float* sbih = su + 384;                // [384]
    float* sbhh = sbih + 384;              // [384]
    float* smb1 = sbhh + 384;              // [128]
    float* smb2 = smb1 + 128;              // [128]

    const int tid = threadIdx.x;
    const int lane = tid & 31, warp = tid >> 5;
    const int lr = lane & 7, lc = lane >> 3;     // 8 x 4 lanes
    const int wr = warp & 1, wc = warp >> 1;     // 2 x 4 warps
    const int r0 = wr * 64 + lr;                 // rows: r0 + 8*i
    const int c0 = (wc * 4 + lc) * 8;            // cols: c0 .. c0+7
    const int bs_idx = blockIdx.x;

    // ---- stage small vectors ----
    for (int t = tid; t < 384; t += 256) {
        su[t] = g_u[t]; sbih[t] = b_ih[t]; sbhh[t] = b_hh[t];
    }
    if (tid < 128) { smb1[tid] = mb1[tid]; smb2[tid] = mb2[tid]; }

    // ---- embedding gather: nf[l][:] = emb[input_var[bs][l]][:]
    {
        const int* iv = input_var + bs_idx * LDIM;
        for (int r = 0; r < 16; ++r) {
            int l = warp * 16 + r;
            int idx = iv[l];
            float4 v = ((const float4*)(emb + (size_t)idx * HDIM))[lane];
            *(float4*)(nf + l * SST + lane * 4) = v;
        }
    }

    // ---- adjacency -> bitmask (each thread builds 2 of the 512 words)
    {
        const float4* ab = (const float4*)(adj + (size_t)bs_idx * LDIM * LDIM);
#pragma unroll
        for (int ww = 0; ww < 2; ++ww) {
            int w = tid * 2 + ww;
            int l = w >> 2, part = w & 3;
            const float4* p = ab + (l * LDIM + part * 32) / 4;
            unsigned m = 0;
#pragma unroll
            for (int q = 0; q < 8; ++q) {
                float4 v = p[q];
                m |= (v.x > 0.5f ? 1u : 0u) << (q * 4 + 0);
                m |= (v.y > 0.5f ? 1u : 0u) << (q * 4 + 1);
                m |= (v.z > 0.5f ? 1u : 0u) << (q * 4 + 2);
                m |= (v.w > 0.5f ? 1u : 0u) << (q * 4 + 3);
            }
            mask[w] = m;
        }
    }
    __syncthreads();
    if (tid < LDIM) {
        deg[tid] = (float)(__popc(mask[tid * 4 + 0]) + __popc(mask[tid * 4 + 1]) +
                           __popc(mask[tid * 4 + 2]) + __popc(mask[tid * 4 + 3]));
    }
    __syncthreads();

    unsigned long long acc2[32];
    float rn[64];   // holds r during n-phase, then n during z-phase

    // ---- 10 GRU iterations, fully in SMEM ----
    for (int it = 0; it < NUM_LOOP; ++it) {
        // s = A @ nf via bitmask gather (warp owns 16 rows; lane owns 4 h cols)
        for (int r = 0; r < 16; ++r) {
            int l = warp * 16 + r;
            float4 a = make_float4(0.f, 0.f, 0.f, 0.f);
#pragma unroll
            for (int w4 = 0; w4 < 4; ++w4) {
                unsigned m = mask[l * 4 + w4];
                while (m) {
                    int c = w4 * 32 + __ffs((int)m) - 1;
                    m &= m - 1;
                    float4 v = *(const float4*)(nf + c * SST + lane * 4);
                    a.x += v.x; a.y += v.y; a.z += v.z; a.w += v.w;
                }
            }
            *(float4*)(sb + l * SST + lane * 4) = a;
        }
        stageB(g_Gt, 384, 0, Bs, tid);        // G_r (overlaps with gather)
        __syncthreads();

        // ================= R gate: r = sigmoid(s@G_r + nf@Whh_r + deg*u_r + b) ======
#pragma unroll
        for (int p = 0; p < 32; ++p) acc2[p] = 0ull;
        gemm2(sb, Bs, acc2, r0, c0);
        __syncthreads();
        stageB(g_Whht, 384, 0, Bs, tid);      // Whh_r
        __syncthreads();
        gemm2(nf, Bs, acc2, r0, c0);
#pragma unroll
        for (int i = 0; i < 8; ++i) {
            int row = r0 + i * 8;
            float dg = deg[row];
#pragma unroll
            for (int j2 = 0; j2 < 4; ++j2) {
                int h = c0 + j2 * 2;
                float2 v = unpk(acc2[i * 4 + j2]);
                rn[i * 8 + j2 * 2 + 0] = fsig(v.x + dg * su[h]     + sbih[h]     + sbhh[h]);
                rn[i * 8 + j2 * 2 + 1] = fsig(v.y + dg * su[h + 1] + sbih[h + 1] + sbhh[h + 1]);
            }
        }

        // ================= n gate: n = tanh(s@G_n + deg*u_n + b_ih_n + r*(nf@Whh_n + b_hh_n))
        __syncthreads();
        stageB(g_Whht, 384, 256, Bs, tid);    // Whh_n
        __syncthreads();
#pragma unroll
        for (int p = 0; p < 32; ++p) acc2[p] = 0ull;
        gemm2(nf, Bs, acc2, r0, c0);
#pragma unroll
        for (int i = 0; i < 8; ++i) {
#pragma unroll
            for (int j2 = 0; j2 < 4; ++j2) {
                int h = c0 + j2 * 2;
                float2 v = unpk(acc2[i * 4 + j2]);
                v.x = rn[i * 8 + j2 * 2 + 0] * (v.x + sbhh[256 + h]);
                v.y = rn[i * 8 + j2 * 2 + 1] * (v.y + sbhh[256 + h + 1]);
                acc2[i * 4 + j2] = pk(v.x, v.y);
            }
        }
        __syncthreads();
        stageB(g_Gt, 384, 256, Bs, tid);      // G_n
        __syncthreads();
        gemm2(sb, Bs, acc2, r0, c0);
#pragma unroll
        for (int i = 0; i < 8; ++i) {
            int row = r0 + i * 8;
            float dg = deg[row];
#pragma unroll
            for (int j2 = 0; j2 < 4; ++j2) {
                int h = c0 + j2 * 2;
                float2 v = unpk(acc2[i * 4 + j2]);
                rn[i * 8 + j2 * 2 + 0] = ftanh(v.x + dg * su[256 + h]     + sbih[256 + h]);
                rn[i * 8 + j2 * 2 + 1] = ftanh(v.y + dg * su[256 + h + 1] + sbih[256 + h + 1]);
            }
        }

        // ================= Z gate + state update: nf = n + z*(nf - n) ================
        __syncthreads();
        stageB(g_Gt, 384, 128, Bs, tid);      // G_z
        __syncthreads();
#pragma unroll
        for (int p = 0; p < 32; ++p) acc2[p] = 0ull;
        gemm2(sb, Bs, acc2, r0, c0);
        __syncthreads();
        stageB(g_Whht, 384, 128, Bs, tid);    // Whh_z
        __syncthreads();
        gemm2(nf, Bs, acc2, r0, c0);
        __syncthreads();   // all gemm reads of nf complete before any write
#pragma unroll
        for (int i = 0; i < 8; ++i) {
            int row = r0 + i * 8;
            float dg = deg[row];
#pragma unroll
            for (int j2 = 0; j2 < 4; ++j2) {
                int h = c0 + j2 * 2;
                float2 v = unpk(acc2[i * 4 + j2]);
                float zx = fsig(v.x + dg * su[128 + h]     + sbih[128 + h]     + sbhh[128 + h]);
                float zy = fsig(v.y + dg * su[128 + h + 1] + sbih[128 + h + 1] + sbhh[128 + h + 1]);
                float2 old = *(const float2*)(nf + row * SST + h);
                float nx = rn[i * 8 + j2 * 2 + 0];
                float ny = rn[i * 8 + j2 * 2 + 1];
                float2 nw;
                nw.x = nx + zx * (old.x - nx);
                nw.y = ny + zy * (old.y - ny);
                *(float2*)(nf + row * SST + h) = nw;
            }
        }
        __syncthreads();   // nf ready for next gather
    }

    // ---- mention MLP ----
    stageB(g_m1t, 128, 0, Bs, tid);
    __syncthreads();
#pragma unroll
    for (int p = 0; p < 32; ++p) acc2[p] = 0ull;
    gemm2(nf, Bs, acc2, r0, c0);
#pragma unroll
    for (int i = 0; i < 8; ++i) {
        int row = r0 + i * 8;
#pragma unroll
        for (int j2 = 0; j2 < 4; ++j2) {
            int h = c0 + j2 * 2;
            float2 v = unpk(acc2[i * 4 + j2]);
            float2 o;
            o.x = ftanh(v.x + smb1[h]);
            o.y = ftanh(v.y + smb1[h + 1]);
            *(float2*)(sb + row * SST + h) = o;
        }
    }
    __syncthreads();
    stageB(g_m2t, 128, 0, Bs, tid);
    __syncthreads();
#pragma unroll
    for (int p = 0; p < 32; ++p) acc2[p] = 0ull;
    gemm2(sb, Bs, acc2, r0, c0);
#pragma unroll
    for (int i = 0; i < 8; ++i) {
        int row = r0 + i * 8;
#pragma unroll
        for (int j2 = 0; j2 < 4; ++j2) {
            int h = c0 + j2 * 2;
            float2 v = unpk(acc2[i * 4 + j2]);
            float2 o;
            o.x = ftanh(v.x + smb2[h]);
            o.y = ftanh(v.y + smb2[h + 1]);
            *(float2*)(nf + row * SST + h) = o;   // h2 into nf (no longer needed)
        }
    }
    __syncthreads();

    if (tid < LDIM) {
        float a = mb3[0];
#pragma unroll 4
        for (int h = 0; h < HDIM; ++h)
            a = fmaf(nf[tid * SST + h], mW3[h], a);
        out[bs_idx * LDIM + tid] = ftanh(a);
    }
}

// ---------------- launch ----------------
extern "C" void kernel_launch(void* const* d_in, const int* in_sizes, int n_in,
                              void* d_out, int out_size) {
    const int*   input_var = (const int*)  d_in[0];
    const float* adjacency = (const float*)d_in[1];
    const float* emb       = (const float*)d_in[2];
    const float* gnn_w     = (const float*)d_in[3];
    const float* gnn_b     = (const float*)d_in[4];
    const float* W_ih      = (const float*)d_in[5];
    const float* W_hh      = (const float*)d_in[6];
    const float* b_ih      = (const float*)d_in[7];
    const float* b_hh      = (const float*)d_in[8];
    const float* mW1       = (const float*)d_in[9];
    const float* mb1       = (const float*)d_in[10];
    const float* mW2       = (const float*)d_in[11];
    const float* mb2       = (const float*)d_in[12];
    const float* mW3       = (const float*)d_in[13];
    const float* mb3       = (const float*)d_in[14];
    float* out = (float*)d_out;

    prep_gemm<<<(128 * 384 + 255) / 256, 256>>>(gnn_w, W_ih, gnn_b);
    prep_trans<<<(128 * 384 + 2 * 128 * 128 + 255) / 256, 256>>>(W_hh, mW1, mW2);

    // smem: nf + sb (128*132 each) + Bs (128*128) + mask(512 u32) + deg(128) + vectors(1408)
    const int smem_floats = 2 * LDIM * SST + 128 * 128 + 512 + 128 + 384 * 3 + 256;
    const int smem_bytes = smem_floats * 4;
    cudaFuncSetAttribute(gnn_main, cudaFuncAttributeMaxDynamicSharedMemorySize, smem_bytes);
    gnn_main<<<NBS, 256, smem_bytes>>>(input_var, adjacency, emb,
                                       b_ih, b_hh, mb1, mb2, mW3, mb3, out);
}

// round 13
// speedup vs baseline: 2.6644x; 2.0478x over previous
#include <cuda_runtime.h>
#include <cuda_bf16.h>
#include <stdint.h>

#define NBS 2048
#define NUM_LOOP 10

// smem byte offsets
#define OFF_NFH 0
#define OFF_NFL 32768
#define OFF_SH  65536
#define OFF_SL  98304
#define OFF_WB0 131072          /* two 32KB weight stage buffers */
#define OFF_MASK 196608
#define OFF_DEG  198656
#define OFF_SU   199168
#define OFF_BIH  200704
#define OFF_BHH  202240
#define OFF_MB1  203776
#define OFF_MB2  204288
#define OFF_W3   204800
#define OFF_RED  205312
#define SMEM_TOTAL 206336

// blocked SW128 bf16 tile addressing: atom 8 rows x 64 cols, atom_off = atom_row + atom_col*16
__host__ __device__ __forceinline__ uint32_t baddr(int row, int col) {
    uint32_t b = ((uint32_t)((row >> 3) + ((col >> 6) << 4)) << 10)
               | ((uint32_t)(row & 7) << 7) | ((uint32_t)(col & 63) << 1);
    return b ^ ((b >> 3) & 0x70);
}

// 8 weight tiles x {hi,lo}, stored [out_n][in_k] (= mma col-major B operand):
// 0..2 G_r/z/n (= gnn_w @ W_ih^T), 3..5 Whh_r/z/n, 6 mW1, 7 mW2
__device__ __align__(16) unsigned short g_w[8][2][128 * 128];
__device__ float g_u[384];

__device__ __forceinline__ void bsplit_store(float v, int tile, int h, int k) {
    __nv_bfloat16 bh = __float2bfloat16_rn(v);
    __nv_bfloat16 bl = __float2bfloat16_rn(v - __bfloat162float(bh));
    uint32_t off = baddr(h, k);
    *(unsigned short*)((char*)g_w[tile][0] + off) = __bfloat16_as_ushort(bh);
    *(unsigned short*)((char*)g_w[tile][1] + off) = __bfloat16_as_ushort(bl);
}

__global__ void prep_g(const float* __restrict__ gnn_w, const float* __restrict__ W_ih,
                       const float* __restrict__ gnn_b) {
    int t = blockIdx.x * blockDim.x + threadIdx.x;
    if (t >= 3 * 16384) return;
    int gate = t >> 14, rem = t & 16383, h = rem >> 7, k = rem & 127;
    const float* a = W_ih + (gate * 128 + h) * 128;
    const float* b = gnn_w + k * 128;
    float acc = 0.f;
#pragma unroll 4
    for (int m = 0; m < 128; ++m) acc = fmaf(a[m], b[m], acc);
    bsplit_store(acc, gate, h, k);
    if (t < 384) {
        const float* a2 = W_ih + t * 128;
        float u = 0.f;
#pragma unroll 4
        for (int m = 0; m < 128; ++m) u = fmaf(gnn_b[m], a2[m], u);
        g_u[t] = u;
    }
}

__global__ void prep_w(const float* __restrict__ W_hh, const float* __restrict__ mW1,
                       const float* __restrict__ mW2) {
    int t = blockIdx.x * blockDim.x + threadIdx.x;
    if (t >= 5 * 16384) return;
    int rem = t & 16383, h = rem >> 7, k = rem & 127;
    float v; int tile;
    if (t < 3 * 16384)      { tile = 3 + (t >> 14); v = W_hh[((t >> 14) * 128 + h) * 128 + k]; }
    else if (t < 4 * 16384) { tile = 6; v = mW1[h * 128 + k]; }
    else                    { tile = 7; v = mW2[h * 128 + k]; }
    bsplit_store(v, tile, h, k);
}

// ---- helpers ----
__device__ __forceinline__ uint32_t smem_u32(const void* p) {
    uint32_t a;
    asm("{ .reg .u64 t; cvta.to.shared.u64 t, %1; cvt.u32.u64 %0, t; }" : "=r"(a) : "l"(p));
    return a;
}
__device__ __forceinline__ float fsig(float x) { return __fdividef(1.0f, 1.0f + __expf(-x)); }
__device__ __forceinline__ float ftanh(float x) { return 1.0f - __fdividef(2.0f, __expf(2.0f * x) + 1.0f); }
__device__ __forceinline__ uint32_t pack_split(float v0, float v1, uint32_t& lo) {
    __nv_bfloat16 h0 = __float2bfloat16_rn(v0), h1 = __float2bfloat16_rn(v1);
    __nv_bfloat16 l0 = __float2bfloat16_rn(v0 - __bfloat162float(h0));
    __nv_bfloat16 l1 = __float2bfloat16_rn(v1 - __bfloat162float(h1));
    lo = (uint32_t)__bfloat16_as_ushort(l0) | ((uint32_t)__bfloat16_as_ushort(l1) << 16);
    return (uint32_t)__bfloat16_as_ushort(h0) | ((uint32_t)__bfloat16_as_ushort(h1) << 16);
}
__device__ __forceinline__ float2 upk2(uint32_t w) {
    __nv_bfloat162 b = *reinterpret_cast<__nv_bfloat162*>(&w);
    return __bfloat1622float2(b);
}
__device__ __forceinline__ void ldsm4(uint32_t* r, uint32_t addr) {
    asm volatile("ldmatrix.sync.aligned.m8n8.x4.shared.b16 {%0,%1,%2,%3}, [%4];"
        : "=r"(r[0]), "=r"(r[1]), "=r"(r[2]), "=r"(r[3]) : "r"(addr));
}
__device__ __forceinline__ void mma16816(float* d, const uint32_t* a, const uint32_t* b) {
    asm volatile("mma.sync.aligned.m16n8k16.row.col.f32.bf16.bf16.f32 "
        "{%0,%1,%2,%3}, {%4,%5,%6,%7}, {%8,%9}, {%0,%1,%2,%3};"
        : "+f"(d[0]), "+f"(d[1]), "+f"(d[2]), "+f"(d[3])
        : "r"(a[0]), "r"(a[1]), "r"(a[2]), "r"(a[3]), "r"(b[0]), "r"(b[1]));
}

// one gemm pass: acc(32m x 64n warp tile) += A[128x128 bf16 @Ab] @ B[128x128 bf16 @Bb]^T
__device__ __forceinline__ void mma_pass(uint32_t Ab, uint32_t Bb, float* acc,
                                         int mrow, int ncol, int lane) {
#pragma unroll 2
    for (int ks = 0; ks < 8; ++ks) {
        int k0 = ks * 16;
        uint32_t a[2][4];
#pragma unroll
        for (int mi = 0; mi < 2; ++mi) {
            int row = mrow + mi * 16 + (lane & 15);
            int col = k0 + ((lane >> 4) << 3);
            ldsm4(a[mi], Ab + baddr(row, col));
        }
        uint32_t b[8][2];
#pragma unroll
        for (int np = 0; np < 4; ++np) {
            uint32_t t[4];
            int nrow = ncol + np * 16 + (lane & 7) + ((lane >> 4) << 3);
            int col  = k0 + (((lane >> 3) & 1) << 3);
            ldsm4(t, Bb + baddr(nrow, col));
            b[np*2][0] = t[0]; b[np*2][1] = t[1];
            b[np*2+1][0] = t[2]; b[np*2+1][1] = t[3];
        }
#pragma unroll
        for (int mi = 0; mi < 2; ++mi)
#pragma unroll
            for (int ni = 0; ni < 8; ++ni)
                mma16816(acc + (mi * 8 + ni) * 4, a[mi], b[ni]);
    }
}

// cp.async weight staging pipeline: parts 0..123; tile table repeats 12/iter then 4 MLP parts
__device__ __forceinline__ void issue_part(int p, uint32_t sb32, int tid) {
    if (p >= 124) return;
    const int PT[16] = {0,0,3,3,5,5,2,2,1,1,4,4,6,6,7,7};
    int i = (p < 120) ? (p % 12) : (12 + (p - 120));
    const char* src = (const char*)g_w[PT[i]][i & 1];
    uint32_t dst = sb32 + OFF_WB0 + (uint32_t)(p & 1) * 32768u;
#pragma unroll
    for (int q = 0; q < 8; ++q) {
        uint32_t off = (uint32_t)(q * 256 + tid) * 16u;
        asm volatile("cp.async.cg.shared.global [%0], [%1], 16;"
                     :: "r"(dst + off), "l"(src + off) : "memory");
    }
    asm volatile("cp.async.commit_group;" ::: "memory");
}
__device__ __forceinline__ void consume_part(int p, uint32_t Ah, uint32_t Al, bool two,
                                             float* acc, uint32_t sb32, int tid,
                                             int mrow, int ncol, int lane) {
    if (p < 122) asm volatile("cp.async.wait_group 1;" ::: "memory");
    else         asm volatile("cp.async.wait_group 0;" ::: "memory");
    __syncthreads();
    uint32_t B = sb32 + OFF_WB0 + (uint32_t)(p & 1) * 32768u;
    mma_pass(Ah, B, acc, mrow, ncol, lane);
    if (two) mma_pass(Al, B, acc, mrow, ncol, lane);
    __syncthreads();
    issue_part(p + 2, sb32, tid);
}

__global__ void __launch_bounds__(256, 1)
gnn_main(const int* __restrict__ input_var, const float* __restrict__ adj,
         const float* __restrict__ emb, const float* __restrict__ b_ih,
         const float* __restrict__ b_hh, const float* __restrict__ mb1,
         const float* __restrict__ mb2, const float* __restrict__ mW3,
         const float* __restrict__ mb3, float* __restrict__ out) {
    extern __shared__ char sm[];
    const uint32_t sb32 = smem_u32(sm);
    const int tid = threadIdx.x, lane = tid & 31, warp = tid >> 5;
    const int bs_idx = blockIdx.x;
    char* nfh = sm + OFF_NFH; char* nfl = sm + OFF_NFL;
    char* shh = sm + OFF_SH;  char* sll = sm + OFF_SL;
    unsigned* mask = (unsigned*)(sm + OFF_MASK);
    float* degp = (float*)(sm + OFF_DEG);
    float* sup  = (float*)(sm + OFF_SU);
    float* bihp = (float*)(sm + OFF_BIH);
    float* bhhp = (float*)(sm + OFF_BHH);
    float* mb1p = (float*)(sm + OFF_MB1);
    float* mb2p = (float*)(sm + OFF_MB2);
    float* w3p  = (float*)(sm + OFF_W3);
    float* redp = (float*)(sm + OFF_RED);

    const int warpM = warp >> 1, warpN = warp & 1;
    const int mrow = warpM * 32, ncol = warpN * 64;
    const int trow0 = mrow + (lane >> 2);
    const int tcol0 = ncol + ((lane & 3) << 1);
    const uint32_t A_NFH = sb32 + OFF_NFH, A_NFL = sb32 + OFF_NFL;
    const uint32_t A_SH  = sb32 + OFF_SH,  A_SL  = sb32 + OFF_SL;

    // prefetch first two weight parts immediately
    issue_part(0, sb32, tid);
    issue_part(1, sb32, tid);

    for (int t = tid; t < 384; t += 256) { sup[t] = g_u[t]; bihp[t] = b_ih[t]; bhhp[t] = b_hh[t]; }
    if (tid < 128) { mb1p[tid] = mb1[tid]; mb2p[tid] = mb2[tid]; w3p[tid] = mW3[tid]; }

    // embedding gather -> nf split
    {
        const int* iv = input_var + bs_idx * 128;
        for (int r = 0; r < 16; ++r) {
            int l = warp * 16 + r;
            float4 v = ((const float4*)(emb + (size_t)iv[l] * 128))[lane];
            uint32_t lo0, lo1, hi0 = pack_split(v.x, v.y, lo0), hi1 = pack_split(v.z, v.w, lo1);
            uint32_t off = baddr(l, lane * 4);
            *(uint2*)(nfh + off) = make_uint2(hi0, hi1);
            *(uint2*)(nfl + off) = make_uint2(lo0, lo1);
        }
    }
    // adjacency -> bitmask
    {
        const float4* ab = (const float4*)(adj + (size_t)bs_idx * 128 * 128);
#pragma unroll
        for (int ww = 0; ww < 2; ++ww) {
            int w = tid * 2 + ww, l = w >> 2, part = w & 3;
            const float4* pp = ab + (l * 128 + part * 32) / 4;
            unsigned m = 0;
#pragma unroll
            for (int q = 0; q < 8; ++q) {
                float4 v = pp[q];
                m |= (v.x > 0.5f) << (q * 4) | (v.y > 0.5f) << (q * 4 + 1)
                   | (v.z > 0.5f) << (q * 4 + 2) | (v.w > 0.5f) << (q * 4 + 3);
            }
            mask[w] = m;
        }
    }
    __syncthreads();
    if (tid < 128)
        degp[tid] = (float)(__popc(mask[tid*4]) + __popc(mask[tid*4+1]) +
                            __popc(mask[tid*4+2]) + __popc(mask[tid*4+3]));
    __syncthreads();

    float acc[64], gate[64];
    float dgv[4];
#pragma unroll
    for (int mi = 0; mi < 2; ++mi)
#pragma unroll
        for (int qr = 0; qr < 2; ++qr)
            dgv[mi * 2 + qr] = degp[trow0 + mi * 16 + qr * 8];

    for (int it = 0; it < NUM_LOOP; ++it) {
        const int p0 = it * 12;
        // s = A @ nf (recombine hi+lo, write split)
        for (int r = 0; r < 16; ++r) {
            int l = warp * 16 + r;
            float a0 = 0.f, a1 = 0.f, a2 = 0.f, a3 = 0.f;
#pragma unroll
            for (int w4 = 0; w4 < 4; ++w4) {
                unsigned m = mask[l * 4 + w4];
                while (m) {
                    int c = w4 * 32 + __ffs((int)m) - 1; m &= m - 1;
                    uint32_t off = baddr(c, lane * 4);
                    uint2 vh = *(uint2*)(nfh + off), vl = *(uint2*)(nfl + off);
                    float2 h0 = upk2(vh.x), h1 = upk2(vh.y), l0 = upk2(vl.x), l1 = upk2(vl.y);
                    a0 += h0.x + l0.x; a1 += h0.y + l0.y; a2 += h1.x + l1.x; a3 += h1.y + l1.y;
                }
            }
            uint32_t lo0, lo1, hi0 = pack_split(a0, a1, lo0), hi1 = pack_split(a2, a3, lo1);
            uint32_t off = baddr(l, lane * 4);
            *(uint2*)(shh + off) = make_uint2(hi0, hi1);
            *(uint2*)(sll + off) = make_uint2(lo0, lo1);
        }
        // ---- r = sigmoid(s@G_r + nf@Whh_r + deg*u + b) ----
#pragma unroll
        for (int i = 0; i < 64; ++i) acc[i] = 0.f;
        consume_part(p0+0, A_SH,  A_SL,  true,  acc, sb32, tid, mrow, ncol, lane);
        consume_part(p0+1, A_SH,  0,     false, acc, sb32, tid, mrow, ncol, lane);
        consume_part(p0+2, A_NFH, A_NFL, true,  acc, sb32, tid, mrow, ncol, lane);
        consume_part(p0+3, A_NFH, 0,     false, acc, sb32, tid, mrow, ncol, lane);
#pragma unroll
        for (int mi = 0; mi < 2; ++mi)
#pragma unroll
            for (int ni = 0; ni < 8; ++ni)
#pragma unroll
                for (int q = 0; q < 4; ++q) {
                    int idx = (mi*8+ni)*4+q, col = tcol0 + ni*8 + (q&1);
                    gate[idx] = fsig(acc[idx] + dgv[mi*2+(q>>1)]*sup[col] + bihp[col] + bhhp[col]);
                }
        // ---- n: acc = nf@Whh_n; gate = r*(acc+bhh_n); acc = s@G_n; n = tanh(acc+deg*u+bih+gate)
#pragma unroll
        for (int i = 0; i < 64; ++i) acc[i] = 0.f;
        consume_part(p0+4, A_NFH, A_NFL, true,  acc, sb32, tid, mrow, ncol, lane);
        consume_part(p0+5, A_NFH, 0,     false, acc, sb32, tid, mrow, ncol, lane);
#pragma unroll
        for (int mi = 0; mi < 2; ++mi)
#pragma unroll
            for (int ni = 0; ni < 8; ++ni)
#pragma unroll
                for (int q = 0; q < 4; ++q) {
                    int idx = (mi*8+ni)*4+q, col = tcol0 + ni*8 + (q&1);
                    gate[idx] *= (acc[idx] + bhhp[256 + col]);
                }
#pragma unroll
        for (int i = 0; i < 64; ++i) acc[i] = 0.f;
        consume_part(p0+6, A_SH, A_SL, true,  acc, sb32, tid, mrow, ncol, lane);
        consume_part(p0+7, A_SH, 0,    false, acc, sb32, tid, mrow, ncol, lane);
#pragma unroll
        for (int mi = 0; mi < 2; ++mi)
#pragma unroll
            for (int ni = 0; ni < 8; ++ni)
#pragma unroll
                for (int q = 0; q < 4; ++q) {
                    int idx = (mi*8+ni)*4+q, col = tcol0 + ni*8 + (q&1);
                    gate[idx] = ftanh(acc[idx] + dgv[mi*2+(q>>1)]*sup[256+col] + bihp[256+col] + gate[idx]);
                }
        // ---- z + update ----
#pragma unroll
        for (int i = 0; i < 64; ++i) acc[i] = 0.f;
        consume_part(p0+8,  A_SH,  A_SL,  true,  acc, sb32, tid, mrow, ncol, lane);
        consume_part(p0+9,  A_SH,  0,     false, acc, sb32, tid, mrow, ncol, lane);
        consume_part(p0+10, A_NFH, A_NFL, true,  acc, sb32, tid, mrow, ncol, lane);
        consume_part(p0+11, A_NFH, 0,     false, acc, sb32, tid, mrow, ncol, lane);
#pragma unroll
        for (int mi = 0; mi < 2; ++mi)
#pragma unroll
            for (int ni = 0; ni < 8; ++ni)
#pragma unroll
                for (int qr = 0; qr < 2; ++qr) {
                    int row = trow0 + mi*16 + qr*8, colp = tcol0 + ni*8;
                    int i0 = (mi*8+ni)*4 + qr*2;
                    float dg = dgv[mi*2+qr];
                    float z0 = fsig(acc[i0]   + dg*sup[128+colp]   + bihp[128+colp]   + bhhp[128+colp]);
                    float z1 = fsig(acc[i0+1] + dg*sup[128+colp+1] + bihp[128+colp+1] + bhhp[128+colp+1]);
                    uint32_t off = baddr(row, colp);
                    float2 oh = upk2(*(uint32_t*)(nfh + off)), ol = upk2(*(uint32_t*)(nfl + off));
                    float o0 = oh.x + ol.x, o1 = oh.y + ol.y;
                    float n0 = gate[i0], n1 = gate[i0+1];
                    float w0 = n0 + z0 * (o0 - n0), w1 = n1 + z1 * (o1 - n1);
                    uint32_t lo, hi = pack_split(w0, w1, lo);
                    *(uint32_t*)(nfh + off) = hi;
                    *(uint32_t*)(nfl + off) = lo;
                }
        __syncthreads();
    }

    // ---- MLP: h1 = tanh(nf@mW1^T + b1) -> sh/sl; h2 = tanh(h1@mW2^T + b2); dot w3 ----
#pragma unroll
    for (int i = 0; i < 64; ++i) acc[i] = 0.f;
    consume_part(120, A_NFH, A_NFL, true,  acc, sb32, tid, mrow, ncol, lane);
    consume_part(121, A_NFH, 0,     false, acc, sb32, tid, mrow, ncol, lane);
#pragma unroll
    for (int mi = 0; mi < 2; ++mi)
#pragma unroll
        for (int ni = 0; ni < 8; ++ni)
#pragma unroll
            for (int qr = 0; qr < 2; ++qr) {
                int row = trow0 + mi*16 + qr*8, colp = tcol0 + ni*8;
                int i0 = (mi*8+ni)*4 + qr*2;
                float v0 = ftanh(acc[i0]   + mb1p[colp]);
                float v1 = ftanh(acc[i0+1] + mb1p[colp+1]);
                uint32_t lo, hi = pack_split(v0, v1, lo);
                uint32_t off = baddr(row, colp);
                *(uint32_t*)(shh + off) = hi;
                *(uint32_t*)(sll + off) = lo;
            }
#pragma unroll
    for (int i = 0; i < 64; ++i) acc[i] = 0.f;
    consume_part(122, A_SH, A_SL, true,  acc, sb32, tid, mrow, ncol, lane);
    consume_part(123, A_SH, 0,    false, acc, sb32, tid, mrow, ncol, lane);
    {
        float rsum[4] = {0.f, 0.f, 0.f, 0.f};
#pragma unroll
        for (int mi = 0; mi < 2; ++mi)
#pragma unroll
            for (int ni = 0; ni < 8; ++ni)
#pragma unroll
                for (int q = 0; q < 4; ++q) {
                    int idx = (mi*8+ni)*4+q, col = tcol0 + ni*8 + (q&1);
                    rsum[mi*2+(q>>1)] += ftanh(acc[idx] + mb2p[col]) * w3p[col];
                }
#pragma unroll
        for (int k = 0; k < 4; ++k) {
            rsum[k] += __shfl_xor_sync(0xFFFFFFFFu, rsum[k], 1);
            rsum[k] += __shfl_xor_sync(0xFFFFFFFFu, rsum[k], 2);
        }
        if ((lane & 3) == 0) {
#pragma unroll
            for (int mi = 0; mi < 2; ++mi)
#pragma unroll
                for (int qr = 0; qr < 2; ++qr)
                    redp[warpN * 128 + trow0 + mi*16 + qr*8] = rsum[mi*2+qr];
        }
    }
    __syncthreads();
    if (tid < 128)
        out[bs_idx * 128 + tid] = ftanh(redp[tid] + redp[128 + tid] + mb3[0]);
}

extern "C" void kernel_launch(void* const* d_in, const int* in_sizes, int n_in,
                              void* d_out, int out_size) {
    const int*   input_var = (const int*)  d_in[0];
    const float* adjacency = (const float*)d_in[1];
    const float* emb       = (const float*)d_in[2];
    const float* gnn_w     = (const float*)d_in[3];
    const float* gnn_b     = (const float*)d_in[4];
    const float* W_ih      = (const float*)d_in[5];
    const float* W_hh      = (const float*)d_in[6];
    const float* b_ih      = (const float*)d_in[7];
    const float* b_hh      = (const float*)d_in[8];
    const float* mW1       = (const float*)d_in[9];
    const float* mb1       = (const float*)d_in[10];
    const float* mW2       = (const float*)d_in[11];
    const float* mb2       = (const float*)d_in[12];
    const float* mW3       = (const float*)d_in[13];
    const float* mb3       = (const float*)d_in[14];
    float* out = (float*)d_out;

    prep_g<<<192, 256>>>(gnn_w, W_ih, gnn_b);
    prep_w<<<320, 256>>>(W_hh, mW1, mW2);

    cudaFuncSetAttribute(gnn_main, cudaFuncAttributeMaxDynamicSharedMemorySize, SMEM_TOTAL);
    gnn_main<<<NBS, 256, SMEM_TOTAL>>>(input_var, adjacency, emb,
                                       b_ih, b_hh, mb1, mb2, mW3, mb3, out);
}

// round 14
// speedup vs baseline: 3.3288x; 1.2494x over previous
#include <cuda_runtime.h>
#include <cuda_fp16.h>
#include <stdint.h>

#define NBS 2048
#define NUM_LOOP 10

// smem byte offsets
#define OFF_NFH 0
#define OFF_NFL 32768
#define OFF_SH  65536
#define OFF_SL  98304
#define OFF_WB0 131072          /* two 32KB weight stage buffers */
#define OFF_MASK 196608
#define OFF_DEG  198656
#define OFF_SU   199168
#define OFF_BIH  200704
#define OFF_BHH  202240
#define OFF_MB1  203776
#define OFF_MB2  204288
#define OFF_W3   204800
#define OFF_RED  205312
#define SMEM_TOTAL 206336

// blocked SW128 fp16 tile addressing: atom 8 rows x 64 cols, atom_off = atom_row + atom_col*16
__host__ __device__ __forceinline__ uint32_t baddr(int row, int col) {
    uint32_t b = ((uint32_t)((row >> 3) + ((col >> 6) << 4)) << 10)
               | ((uint32_t)(row & 7) << 7) | ((uint32_t)(col & 63) << 1);
    return b ^ ((b >> 3) & 0x70);
}

// 8 weight tiles x {hi,lo} fp16, stored [out_n][in_k] (mma col-major B):
// 0..2 G_r/z/n (= gnn_w @ W_ih^T), 3..5 Whh_r/z/n, 6 mW1, 7 mW2
__device__ __align__(16) unsigned short g_w[8][2][128 * 128];
__device__ float g_u[384];

__device__ __forceinline__ void hsplit_store(float v, int tile, int h, int k) {
    __half hh = __float2half_rn(v);
    __half hl = __float2half_rn(v - __half2float(hh));
    uint32_t off = baddr(h, k);
    *(unsigned short*)((char*)g_w[tile][0] + off) = __half_as_ushort(hh);
    *(unsigned short*)((char*)g_w[tile][1] + off) = __half_as_ushort(hl);
}

__global__ void prep_g(const float* __restrict__ gnn_w, const float* __restrict__ W_ih,
                       const float* __restrict__ gnn_b) {
    int t = blockIdx.x * blockDim.x + threadIdx.x;
    if (t >= 3 * 16384) return;
    int gate = t >> 14, rem = t & 16383, h = rem >> 7, k = rem & 127;
    const float* a = W_ih + (gate * 128 + h) * 128;
    const float* b = gnn_w + k * 128;
    float acc = 0.f;
#pragma unroll 4
    for (int m = 0; m < 128; ++m) acc = fmaf(a[m], b[m], acc);
    hsplit_store(acc, gate, h, k);
    if (t < 384) {
        const float* a2 = W_ih + t * 128;
        float u = 0.f;
#pragma unroll 4
        for (int m = 0; m < 128; ++m) u = fmaf(gnn_b[m], a2[m], u);
        g_u[t] = u;
    }
}

__global__ void prep_w(const float* __restrict__ W_hh, const float* __restrict__ mW1,
                       const float* __restrict__ mW2) {
    int t = blockIdx.x * blockDim.x + threadIdx.x;
    if (t >= 5 * 16384) return;
    int rem = t & 16383, h = rem >> 7, k = rem & 127;
    float v; int tile;
    if (t < 3 * 16384)      { tile = 3 + (t >> 14); v = W_hh[((t >> 14) * 128 + h) * 128 + k]; }
    else if (t < 4 * 16384) { tile = 6; v = mW1[h * 128 + k]; }
    else                    { tile = 7; v = mW2[h * 128 + k]; }
    hsplit_store(v, tile, h, k);
}

// ---- helpers ----
__device__ __forceinline__ uint32_t smem_u32(const void* p) {
    uint32_t a;
    asm("{ .reg .u64 t; cvta.to.shared.u64 t, %1; cvt.u32.u64 %0, t; }" : "=r"(a) : "l"(p));
    return a;
}
__device__ __forceinline__ float fsig(float x) { return __fdividef(1.0f, 1.0f + __expf(-x)); }
__device__ __forceinline__ float ftanh(float x) { return 1.0f - __fdividef(2.0f, __expf(2.0f * x) + 1.0f); }
// pack two floats into one fp16x2 word (hi image), and the residual lo word
__device__ __forceinline__ uint32_t pack_split(float v0, float v1, uint32_t& lo) {
    __half h0 = __float2half_rn(v0), h1 = __float2half_rn(v1);
    __half l0 = __float2half_rn(v0 - __half2float(h0));
    __half l1 = __float2half_rn(v1 - __half2float(h1));
    lo = (uint32_t)__half_as_ushort(l0) | ((uint32_t)__half_as_ushort(l1) << 16);
    return (uint32_t)__half_as_ushort(h0) | ((uint32_t)__half_as_ushort(h1) << 16);
}
__device__ __forceinline__ uint32_t pack_h2(float v0, float v1) {
    __half2 h = __floats2half2_rn(v0, v1);
    return *reinterpret_cast<uint32_t*>(&h);
}
__device__ __forceinline__ float2 upk2(uint32_t w) {
    __half2 h = *reinterpret_cast<__half2*>(&w);
    return __half22float2(h);
}
__device__ __forceinline__ void ldsm4(uint32_t* r, uint32_t addr) {
    asm volatile("ldmatrix.sync.aligned.m8n8.x4.shared.b16 {%0,%1,%2,%3}, [%4];"
        : "=r"(r[0]), "=r"(r[1]), "=r"(r[2]), "=r"(r[3]) : "r"(addr));
}
__device__ __forceinline__ void mma16816(float* d, const uint32_t* a, const uint32_t* b) {
    asm volatile("mma.sync.aligned.m16n8k16.row.col.f32.f16.f16.f32 "
        "{%0,%1,%2,%3}, {%4,%5,%6,%7}, {%8,%9}, {%0,%1,%2,%3};"
        : "+f"(d[0]), "+f"(d[1]), "+f"(d[2]), "+f"(d[3])
        : "r"(a[0]), "r"(a[1]), "r"(a[2]), "r"(a[3]), "r"(b[0]), "r"(b[1]));
}

// one gemm pass: acc(32m x 64n warp tile) += A[128x128 @Ab] @ B[128x128 @Bb]^T
__device__ __forceinline__ void mma_pass(uint32_t Ab, uint32_t Bb, float* acc,
                                         int mrow, int ncol, int lane) {
#pragma unroll 2
    for (int ks = 0; ks < 8; ++ks) {
        int k0 = ks * 16;
        uint32_t a[2][4];
#pragma unroll
        for (int mi = 0; mi < 2; ++mi) {
            int row = mrow + mi * 16 + (lane & 15);
            int col = k0 + ((lane >> 4) << 3);
            ldsm4(a[mi], Ab + baddr(row, col));
        }
        uint32_t b[8][2];
#pragma unroll
        for (int np = 0; np < 4; ++np) {
            uint32_t t[4];
            int nrow = ncol + np * 16 + (lane & 7) + ((lane >> 4) << 3);
            int col  = k0 + (((lane >> 3) & 1) << 3);
            ldsm4(t, Bb + baddr(nrow, col));
            b[np*2][0] = t[0]; b[np*2][1] = t[1];
            b[np*2+1][0] = t[2]; b[np*2+1][1] = t[3];
        }
#pragma unroll
        for (int mi = 0; mi < 2; ++mi)
#pragma unroll
            for (int ni = 0; ni < 8; ++ni)
                mma16816(acc + (mi * 8 + ni) * 4, a[mi], b[ni]);
    }
}

// cp.async weight staging pipeline: parts 0..123; 12/iter then 4 MLP parts
__device__ __forceinline__ void issue_part(int p, uint32_t sb32, int tid) {
    if (p >= 124) return;
    const int PT[16] = {0,0,3,3,5,5,2,2,1,1,4,4,6,6,7,7};
    int i = (p < 120) ? (p % 12) : (12 + (p - 120));
    const char* src = (const char*)g_w[PT[i]][i & 1];
    uint32_t dst = sb32 + OFF_WB0 + (uint32_t)(p & 1) * 32768u;
#pragma unroll
    for (int q = 0; q < 8; ++q) {
        uint32_t off = (uint32_t)(q * 256 + tid) * 16u;
        asm volatile("cp.async.cg.shared.global [%0], [%1], 16;"
                     :: "r"(dst + off), "l"(src + off) : "memory");
    }
    asm volatile("cp.async.commit_group;" ::: "memory");
}
__device__ __forceinline__ void consume_part(int p, uint32_t Ah, uint32_t Al, bool two,
                                             float* acc, uint32_t sb32, int tid,
                                             int mrow, int ncol, int lane) {
    if (p < 122) asm volatile("cp.async.wait_group 1;" ::: "memory");
    else         asm volatile("cp.async.wait_group 0;" ::: "memory");
    __syncthreads();
    uint32_t B = sb32 + OFF_WB0 + (uint32_t)(p & 1) * 32768u;
    mma_pass(Ah, B, acc, mrow, ncol, lane);
    if (two) mma_pass(Al, B, acc, mrow, ncol, lane);
    __syncthreads();
    issue_part(p + 2, sb32, tid);
}

__global__ void __launch_bounds__(256, 1)
gnn_main(const int* __restrict__ input_var, const float* __restrict__ adj,
         const float* __restrict__ emb, const float* __restrict__ b_ih,
         const float* __restrict__ b_hh, const float* __restrict__ mb1,
         const float* __restrict__ mb2, const float* __restrict__ mW3,
         const float* __restrict__ mb3, float* __restrict__ out) {
    extern __shared__ char sm[];
    const uint32_t sb32 = smem_u32(sm);
    const int tid = threadIdx.x, lane = tid & 31, warp = tid >> 5;
    const int bs_idx = blockIdx.x;
    char* nfh = sm + OFF_NFH; char* nfl = sm + OFF_NFL;
    char* shh = sm + OFF_SH;  char* sll = sm + OFF_SL;
    unsigned* mask = (unsigned*)(sm + OFF_MASK);
    float* degp = (float*)(sm + OFF_DEG);
    float* sup  = (float*)(sm + OFF_SU);
    float* bihp = (float*)(sm + OFF_BIH);
    float* bhhp = (float*)(sm + OFF_BHH);
    float* mb1p = (float*)(sm + OFF_MB1);
    float* mb2p = (float*)(sm + OFF_MB2);
    float* w3p  = (float*)(sm + OFF_W3);
    float* redp = (float*)(sm + OFF_RED);

    const int warpM = warp >> 1, warpN = warp & 1;
    const int mrow = warpM * 32, ncol = warpN * 64;
    const int trow0 = mrow + (lane >> 2);
    const int tcol0 = ncol + ((lane & 3) << 1);
    const uint32_t A_NFH = sb32 + OFF_NFH, A_NFL = sb32 + OFF_NFL;
    const uint32_t A_SH  = sb32 + OFF_SH,  A_SL  = sb32 + OFF_SL;

    issue_part(0, sb32, tid);
    issue_part(1, sb32, tid);

    for (int t = tid; t < 384; t += 256) { sup[t] = g_u[t]; bihp[t] = b_ih[t]; bhhp[t] = b_hh[t]; }
    if (tid < 128) { mb1p[tid] = mb1[tid]; mb2p[tid] = mb2[tid]; w3p[tid] = mW3[tid]; }

    // embedding gather -> nf split (state at ~2^-22 precision; MMA reads hi only)
    {
        const int* iv = input_var + bs_idx * 128;
        for (int r = 0; r < 16; ++r) {
            int l = warp * 16 + r;
            float4 v = ((const float4*)(emb + (size_t)iv[l] * 128))[lane];
            uint32_t lo0, lo1, hi0 = pack_split(v.x, v.y, lo0), hi1 = pack_split(v.z, v.w, lo1);
            uint32_t off = baddr(l, lane * 4);
            *(uint2*)(nfh + off) = make_uint2(hi0, hi1);
            *(uint2*)(nfl + off) = make_uint2(lo0, lo1);
        }
    }
    // adjacency -> bitmask
    {
        const float4* ab = (const float4*)(adj + (size_t)bs_idx * 128 * 128);
#pragma unroll
        for (int ww = 0; ww < 2; ++ww) {
            int w = tid * 2 + ww, l = w >> 2, part = w & 3;
            const float4* pp = ab + (l * 128 + part * 32) / 4;
            unsigned m = 0;
#pragma unroll
            for (int q = 0; q < 8; ++q) {
                float4 v = pp[q];
                m |= (v.x > 0.5f) << (q * 4) | (v.y > 0.5f) << (q * 4 + 1)
                   | (v.z > 0.5f) << (q * 4 + 2) | (v.w > 0.5f) << (q * 4 + 3);
            }
            mask[w] = m;
        }
    }
    __syncthreads();
    if (tid < 128)
        degp[tid] = (float)(__popc(mask[tid*4]) + __popc(mask[tid*4+1]) +
                            __popc(mask[tid*4+2]) + __popc(mask[tid*4+3]));
    __syncthreads();

    float acc[64], gate[64];
    float dgv[4];
#pragma unroll
    for (int mi = 0; mi < 2; ++mi)
#pragma unroll
        for (int qr = 0; qr < 2; ++qr)
            dgv[mi * 2 + qr] = degp[trow0 + mi * 16 + qr * 8];

    for (int it = 0; it < NUM_LOOP; ++it) {
        const int p0 = it * 12;
        // s = A @ nf (reconstruct hi+lo for full state precision; write single fp16 image)
        for (int r = 0; r < 16; ++r) {
            int l = warp * 16 + r;
            float a0 = 0.f, a1 = 0.f, a2 = 0.f, a3 = 0.f;
#pragma unroll
            for (int w4 = 0; w4 < 4; ++w4) {
                unsigned m = mask[l * 4 + w4];
                while (m) {
                    int c = w4 * 32 + __ffs((int)m) - 1; m &= m - 1;
                    uint32_t off = baddr(c, lane * 4);
                    uint2 vh = *(uint2*)(nfh + off), vl = *(uint2*)(nfl + off);
                    float2 h0 = upk2(vh.x), h1 = upk2(vh.y), l0 = upk2(vl.x), l1 = upk2(vl.y);
                    a0 += h0.x + l0.x; a1 += h0.y + l0.y; a2 += h1.x + l1.x; a3 += h1.y + l1.y;
                }
            }
            uint32_t off = baddr(l, lane * 4);
            *(uint2*)(shh + off) = make_uint2(pack_h2(a0, a1), pack_h2(a2, a3));
        }
        // ---- r = sigmoid(s@G_r + nf@Whh_r + deg*u + b) : 2-pass per gemm (B hi, B lo)
#pragma unroll
        for (int i = 0; i < 64; ++i) acc[i] = 0.f;
        consume_part(p0+0, A_SH,  0, false, acc, sb32, tid, mrow, ncol, lane);
        consume_part(p0+1, A_SH,  0, false, acc, sb32, tid, mrow, ncol, lane);
        consume_part(p0+2, A_NFH, 0, false, acc, sb32, tid, mrow, ncol, lane);
        consume_part(p0+3, A_NFH, 0, false, acc, sb32, tid, mrow, ncol, lane);
#pragma unroll
        for (int mi = 0; mi < 2; ++mi)
#pragma unroll
            for (int ni = 0; ni < 8; ++ni)
#pragma unroll
                for (int q = 0; q < 4; ++q) {
                    int idx = (mi*8+ni)*4+q, col = tcol0 + ni*8 + (q&1);
                    gate[idx] = fsig(acc[idx] + dgv[mi*2+(q>>1)]*sup[col] + bihp[col] + bhhp[col]);
                }
        // ---- n ----
#pragma unroll
        for (int i = 0; i < 64; ++i) acc[i] = 0.f;
        consume_part(p0+4, A_NFH, 0, false, acc, sb32, tid, mrow, ncol, lane);
        consume_part(p0+5, A_NFH, 0, false, acc, sb32, tid, mrow, ncol, lane);
#pragma unroll
        for (int mi = 0; mi < 2; ++mi)
#pragma unroll
            for (int ni = 0; ni < 8; ++ni)
#pragma unroll
                for (int q = 0; q < 4; ++q) {
                    int idx = (mi*8+ni)*4+q, col = tcol0 + ni*8 + (q&1);
                    gate[idx] *= (acc[idx] + bhhp[256 + col]);
                }
#pragma unroll
        for (int i = 0; i < 64; ++i) acc[i] = 0.f;
        consume_part(p0+6, A_SH, 0, false, acc, sb32, tid, mrow, ncol, lane);
        consume_part(p0+7, A_SH, 0, false, acc, sb32, tid, mrow, ncol, lane);
#pragma unroll
        for (int mi = 0; mi < 2; ++mi)
#pragma unroll
            for (int ni = 0; ni < 8; ++ni)
#pragma unroll
                for (int q = 0; q < 4; ++q) {
                    int idx = (mi*8+ni)*4+q, col = tcol0 + ni*8 + (q&1);
                    gate[idx] = ftanh(acc[idx] + dgv[mi*2+(q>>1)]*sup[256+col] + bihp[256+col] + gate[idx]);
                }
        // ---- z + update ----
#pragma unroll
        for (int i = 0; i < 64; ++i) acc[i] = 0.f;
        consume_part(p0+8,  A_SH,  0, false, acc, sb32, tid, mrow, ncol, lane);
        consume_part(p0+9,  A_SH,  0, false, acc, sb32, tid, mrow, ncol, lane);
        consume_part(p0+10, A_NFH, 0, false, acc, sb32, tid, mrow, ncol, lane);
        consume_part(p0+11, A_NFH, 0, false, acc, sb32, tid, mrow, ncol, lane);
#pragma unroll
        for (int mi = 0; mi < 2; ++mi)
#pragma unroll
            for (int ni = 0; ni < 8; ++ni)
#pragma unroll
                for (int qr = 0; qr < 2; ++qr) {
                    int row = trow0 + mi*16 + qr*8, colp = tcol0 + ni*8;
                    int i0 = (mi*8+ni)*4 + qr*2;
                    float dg = dgv[mi*2+qr];
                    float z0 = fsig(acc[i0]   + dg*sup[128+colp]   + bihp[128+colp]   + bhhp[128+colp]);
                    float z1 = fsig(acc[i0+1] + dg*sup[128+colp+1] + bihp[128+colp+1] + bhhp[128+colp+1]);
                    uint32_t off = baddr(row, colp);
                    float2 oh = upk2(*(uint32_t*)(nfh + off)), ol = upk2(*(uint32_t*)(nfl + off));
                    float o0 = oh.x + ol.x, o1 = oh.y + ol.y;
                    float n0 = gate[i0], n1 = gate[i0+1];
                    float w0 = n0 + z0 * (o0 - n0), w1 = n1 + z1 * (o1 - n1);
                    uint32_t lo, hi = pack_split(w0, w1, lo);
                    *(uint32_t*)(nfh + off) = hi;
                    *(uint32_t*)(nfl + off) = lo;
                }
        __syncthreads();
    }

    // ---- MLP: kept at 3-pass (split A) for output fidelity ----
#pragma unroll
    for (int i = 0; i < 64; ++i) acc[i] = 0.f;
    consume_part(120, A_NFH, A_NFL, true,  acc, sb32, tid, mrow, ncol, lane);
    consume_part(121, A_NFH, 0,     false, acc, sb32, tid, mrow, ncol, lane);
#pragma unroll
    for (int mi = 0; mi < 2; ++mi)
#pragma unroll
        for (int ni = 0; ni < 8; ++ni)
#pragma unroll
            for (int qr = 0; qr < 2; ++qr) {
                int row = trow0 + mi*16 + qr*8, colp = tcol0 + ni*8;
                int i0 = (mi*8+ni)*4 + qr*2;
                float v0 = ftanh(acc[i0]   + mb1p[colp]);
                float v1 = ftanh(acc[i0+1] + mb1p[colp+1]);
                uint32_t lo, hi = pack_split(v0, v1, lo);
                uint32_t off = baddr(row, colp);
                *(uint32_t*)(shh + off) = hi;
                *(uint32_t*)(sll + off) = lo;
            }
#pragma unroll
    for (int i = 0; i < 64; ++i) acc[i] = 0.f;
    consume_part(122, A_SH, A_SL, true,  acc, sb32, tid, mrow, ncol, lane);
    consume_part(123, A_SH, 0,    false, acc, sb32, tid, mrow, ncol, lane);
    {
        float rsum[4] = {0.f, 0.f, 0.f, 0.f};
#pragma unroll
        for (int mi = 0; mi < 2; ++mi)
#pragma unroll
            for (int ni = 0; ni < 8; ++ni)
#pragma unroll
                for (int q = 0; q < 4; ++q) {
                    int idx = (mi*8+ni)*4+q, col = tcol0 + ni*8 + (q&1);
                    rsum[mi*2+(q>>1)] += ftanh(acc[idx] + mb2p[col]) * w3p[col];
                }
#pragma unroll
        for (int k = 0; k < 4; ++k) {
            rsum[k] += __shfl_xor_sync(0xFFFFFFFFu, rsum[k], 1);
            rsum[k] += __shfl_xor_sync(0xFFFFFFFFu, rsum[k], 2);
        }
        if ((lane & 3) == 0) {
#pragma unroll
            for (int mi = 0; mi < 2; ++mi)
#pragma unroll
                for (int qr = 0; qr < 2; ++qr)
                    redp[warpN * 128 + trow0 + mi*16 + qr*8] = rsum[mi*2+qr];
        }
    }
    __syncthreads();
    if (tid < 128)
        out[bs_idx * 128 + tid] = ftanh(redp[tid] + redp[128 + tid] + mb3[0]);
}

extern "C" void kernel_launch(void* const* d_in, const int* in_sizes, int n_in,
                              void* d_out, int out_size) {
    const int*   input_var = (const int*)  d_in[0];
    const float* adjacency = (const float*)d_in[1];
    const float* emb       = (const float*)d_in[2];
    const float* gnn_w     = (const float*)d_in[3];
    const float* gnn_b     = (const float*)d_in[4];
    const float* W_ih      = (const float*)d_in[5];
    const float* W_hh      = (const float*)d_in[6];
    const float* b_ih      = (const float*)d_in[7];
    const float* b_hh      = (const float*)d_in[8];
    const float* mW1       = (const float*)d_in[9];
    const float* mb1       = (const float*)d_in[10];
    const float* mW2       = (const float*)d_in[11];
    const float* mb2       = (const float*)d_in[12];
    const float* mW3       = (const float*)d_in[13];
    const float* mb3       = (const float*)d_in[14];
    float* out = (float*)d_out;

    prep_g<<<192, 256>>>(gnn_w, W_ih, gnn_b);
    prep_w<<<320, 256>>>(W_hh, mW1, mW2);

    cudaFuncSetAttribute(gnn_main, cudaFuncAttributeMaxDynamicSharedMemorySize, SMEM_TOTAL);
    gnn_main<<<NBS, 256, SMEM_TOTAL>>>(input_var, adjacency, emb,
                                       b_ih, b_hh, mb1, mb2, mW3, mb3, out);
}

// round 15
// speedup vs baseline: 4.5180x; 1.3573x over previous
#include <cuda_runtime.h>
#include <cuda_fp16.h>
#include <stdint.h>

#define NBS 2048
#define NUM_LOOP 10

// smem byte offsets
#define OFF_NFH 0
#define OFF_NFL 32768
#define OFF_SH  65536
#define OFF_WB0 98304           /* three 32KB weight stage buffers */
#define OFF_MASK 196608
#define OFF_DEG  198656
#define OFF_SU   199168
#define OFF_BIH  200704
#define OFF_BHH  202240
#define OFF_MB1  203776
#define OFF_MB2  204288
#define OFF_W3   204800
#define OFF_RED  205312
#define SMEM_TOTAL 206336

// blocked SW128 fp16 tile addressing: atom 8 rows x 64 cols, atom_off = atom_row + atom_col*16
__host__ __device__ __forceinline__ uint32_t baddr(int row, int col) {
    uint32_t b = ((uint32_t)((row >> 3) + ((col >> 6) << 4)) << 10)
               | ((uint32_t)(row & 7) << 7) | ((uint32_t)(col & 63) << 1);
    return b ^ ((b >> 3) & 0x70);
}

// 8 weight tiles x {hi,lo} fp16, [out_n][in_k]: 0..2 G_r/z/n, 3..5 Whh_r/z/n, 6 mW1, 7 mW2
__device__ __align__(16) unsigned short g_w[8][2][128 * 128];
__device__ float g_u[384];

__device__ __forceinline__ void hsplit_store(float v, int tile, int h, int k) {
    __half hh = __float2half_rn(v);
    __half hl = __float2half_rn(v - __half2float(hh));
    uint32_t off = baddr(h, k);
    *(unsigned short*)((char*)g_w[tile][0] + off) = __half_as_ushort(hh);
    *(unsigned short*)((char*)g_w[tile][1] + off) = __half_as_ushort(hl);
}

__global__ void prep_g(const float* __restrict__ gnn_w, const float* __restrict__ W_ih,
                       const float* __restrict__ gnn_b) {
    int t = blockIdx.x * blockDim.x + threadIdx.x;
    if (t >= 3 * 16384) return;
    int gate = t >> 14, rem = t & 16383, h = rem >> 7, k = rem & 127;
    const float* a = W_ih + (gate * 128 + h) * 128;
    const float* b = gnn_w + k * 128;
    float acc = 0.f;
#pragma unroll 4
    for (int m = 0; m < 128; ++m) acc = fmaf(a[m], b[m], acc);
    hsplit_store(acc, gate, h, k);
    if (t < 384) {
        const float* a2 = W_ih + t * 128;
        float u = 0.f;
#pragma unroll 4
        for (int m = 0; m < 128; ++m) u = fmaf(gnn_b[m], a2[m], u);
        g_u[t] = u;
    }
}

__global__ void prep_w(const float* __restrict__ W_hh, const float* __restrict__ mW1,
                       const float* __restrict__ mW2) {
    int t = blockIdx.x * blockDim.x + threadIdx.x;
    if (t >= 5 * 16384) return;
    int rem = t & 16383, h = rem >> 7, k = rem & 127;
    float v; int tile;
    if (t < 3 * 16384)      { tile = 3 + (t >> 14); v = W_hh[((t >> 14) * 128 + h) * 128 + k]; }
    else if (t < 4 * 16384) { tile = 6; v = mW1[h * 128 + k]; }
    else                    { tile = 7; v = mW2[h * 128 + k]; }
    hsplit_store(v, tile, h, k);
}

// ---- helpers ----
__device__ __forceinline__ uint32_t smem_u32(const void* p) {
    uint32_t a;
    asm("{ .reg .u64 t; cvta.to.shared.u64 t, %1; cvt.u32.u64 %0, t; }" : "=r"(a) : "l"(p));
    return a;
}
__device__ __forceinline__ float fsig(float x) { return __fdividef(1.0f, 1.0f + __expf(-x)); }
__device__ __forceinline__ float ftanh(float x) { return 1.0f - __fdividef(2.0f, __expf(2.0f * x) + 1.0f); }
__device__ __forceinline__ uint32_t pack_split(float v0, float v1, uint32_t& lo) {
    __half h0 = __float2half_rn(v0), h1 = __float2half_rn(v1);
    __half l0 = __float2half_rn(v0 - __half2float(h0));
    __half l1 = __float2half_rn(v1 - __half2float(h1));
    lo = (uint32_t)__half_as_ushort(l0) | ((uint32_t)__half_as_ushort(l1) << 16);
    return (uint32_t)__half_as_ushort(h0) | ((uint32_t)__half_as_ushort(h1) << 16);
}
__device__ __forceinline__ uint32_t pack_h2(float v0, float v1) {
    __half2 h = __floats2half2_rn(v0, v1);
    return *reinterpret_cast<uint32_t*>(&h);
}
__device__ __forceinline__ float2 upk2(uint32_t w) {
    __half2 h = *reinterpret_cast<__half2*>(&w);
    return __half22float2(h);
}
__device__ __forceinline__ void ldsm4(uint32_t* r, uint32_t addr) {
    asm volatile("ldmatrix.sync.aligned.m8n8.x4.shared.b16 {%0,%1,%2,%3}, [%4];"
        : "=r"(r[0]), "=r"(r[1]), "=r"(r[2]), "=r"(r[3]) : "r"(addr));
}
__device__ __forceinline__ void mma16816(float* d, const uint32_t* a, const uint32_t* b) {
    asm volatile("mma.sync.aligned.m16n8k16.row.col.f32.f16.f16.f32 "
        "{%0,%1,%2,%3}, {%4,%5,%6,%7}, {%8,%9}, {%0,%1,%2,%3};"
        : "+f"(d[0]), "+f"(d[1]), "+f"(d[2]), "+f"(d[3])
        : "r"(a[0]), "r"(a[1]), "r"(a[2]), "r"(a[3]), "r"(b[0]), "r"(b[1]));
}

// one gemm pass: acc(32m x 64n warp tile) += A[128x128 @Ab] @ B[128x128 @Bb]^T
__device__ __forceinline__ void mma_pass(uint32_t Ab, uint32_t Bb, float* acc,
                                         int mrow, int ncol, int lane) {
#pragma unroll 2
    for (int ks = 0; ks < 8; ++ks) {
        int k0 = ks * 16;
        uint32_t a[2][4];
#pragma unroll
        for (int mi = 0; mi < 2; ++mi) {
            int row = mrow + mi * 16 + (lane & 15);
            int col = k0 + ((lane >> 4) << 3);
            ldsm4(a[mi], Ab + baddr(row, col));
        }
        uint32_t b[8][2];
#pragma unroll
        for (int np = 0; np < 4; ++np) {
            uint32_t t[4];
            int nrow = ncol + np * 16 + (lane & 7) + ((lane >> 4) << 3);
            int col  = k0 + (((lane >> 3) & 1) << 3);
            ldsm4(t, Bb + baddr(nrow, col));
            b[np*2][0] = t[0]; b[np*2][1] = t[1];
            b[np*2+1][0] = t[2]; b[np*2+1][1] = t[3];
        }
#pragma unroll
        for (int mi = 0; mi < 2; ++mi)
#pragma unroll
            for (int ni = 0; ni < 8; ++ni)
                mma16816(acc + (mi * 8 + ni) * 4, a[mi], b[ni]);
    }
}

// weight staging: parts 0..63. Per-iter 6 parts (GRU, hi images only) then 4 MLP parts (hi+lo).
#define LAST_PART 63
__device__ __forceinline__ void issue_part(int p, uint32_t sb32, int tid) {
    if (p > LAST_PART) return;
    int tile, sel;
    if (p < 60) { const int PT6[6] = {0, 3, 5, 2, 1, 4}; tile = PT6[p % 6]; sel = 0; }
    else        { const int MT[4] = {6, 6, 7, 7}; tile = MT[p - 60]; sel = (p - 60) & 1; }
    const char* src = (const char*)g_w[tile][sel];
    uint32_t dst = sb32 + OFF_WB0 + (uint32_t)(p % 3) * 32768u;
#pragma unroll
    for (int q = 0; q < 8; ++q) {
        uint32_t off = (uint32_t)(q * 256 + tid) * 16u;
        asm volatile("cp.async.cg.shared.global [%0], [%1], 16;"
                     :: "r"(dst + off), "l"(src + off) : "memory");
    }
    asm volatile("cp.async.commit_group;" ::: "memory");
}
// consume: wait for part p, sync, prefetch p+2 (distinct buffer, prior readers done), mma.
__device__ __forceinline__ void consume_part(int p, uint32_t Ah, uint32_t Al, bool two,
                                             float* acc, uint32_t sb32, int tid,
                                             int mrow, int ncol, int lane) {
    if (p < LAST_PART) asm volatile("cp.async.wait_group 1;" ::: "memory");
    else               asm volatile("cp.async.wait_group 0;" ::: "memory");
    __syncthreads();
    issue_part(p + 2, sb32, tid);
    uint32_t B = sb32 + OFF_WB0 + (uint32_t)(p % 3) * 32768u;
    mma_pass(Ah, B, acc, mrow, ncol, lane);
    if (two) mma_pass(Al, B, acc, mrow, ncol, lane);
}

__global__ void __launch_bounds__(256, 1)
gnn_main(const int* __restrict__ input_var, const float* __restrict__ adj,
         const float* __restrict__ emb, const float* __restrict__ b_ih,
         const float* __restrict__ b_hh, const float* __restrict__ mb1,
         const float* __restrict__ mb2, const float* __restrict__ mW3,
         const float* __restrict__ mb3, float* __restrict__ out) {
    extern __shared__ char sm[];
    const uint32_t sb32 = smem_u32(sm);
    const int tid = threadIdx.x, lane = tid & 31, warp = tid >> 5;
    const int bs_idx = blockIdx.x;
    char* nfh = sm + OFF_NFH; char* nfl = sm + OFF_NFL;
    char* shh = sm + OFF_SH;
    unsigned* mask = (unsigned*)(sm + OFF_MASK);
    float* degp = (float*)(sm + OFF_DEG);
    float* sup  = (float*)(sm + OFF_SU);
    float* bihp = (float*)(sm + OFF_BIH);
    float* bhhp = (float*)(sm + OFF_BHH);
    float* mb1p = (float*)(sm + OFF_MB1);
    float* mb2p = (float*)(sm + OFF_MB2);
    float* w3p  = (float*)(sm + OFF_W3);
    float* redp = (float*)(sm + OFF_RED);

    const int warpM = warp >> 1, warpN = warp & 1;
    const int mrow = warpM * 32, ncol = warpN * 64;
    const int trow0 = mrow + (lane >> 2);
    const int tcol0 = ncol + ((lane & 3) << 1);
    const uint32_t A_NFH = sb32 + OFF_NFH, A_NFL = sb32 + OFF_NFL;
    const uint32_t A_SH  = sb32 + OFF_SH;

    issue_part(0, sb32, tid);
    issue_part(1, sb32, tid);

    for (int t = tid; t < 384; t += 256) { sup[t] = g_u[t]; bihp[t] = b_ih[t]; bhhp[t] = b_hh[t]; }
    if (tid < 128) { mb1p[tid] = mb1[tid]; mb2p[tid] = mb2[tid]; w3p[tid] = mW3[tid]; }

    // embedding gather -> nf hi/lo split (state at ~2^-22; MMA reads hi image)
    {
        const int* iv = input_var + bs_idx * 128;
        for (int r = 0; r < 16; ++r) {
            int l = warp * 16 + r;
            float4 v = ((const float4*)(emb + (size_t)iv[l] * 128))[lane];
            uint32_t lo0, lo1, hi0 = pack_split(v.x, v.y, lo0), hi1 = pack_split(v.z, v.w, lo1);
            uint32_t off = baddr(l, lane * 4);
            *(uint2*)(nfh + off) = make_uint2(hi0, hi1);
            *(uint2*)(nfl + off) = make_uint2(lo0, lo1);
        }
    }
    // adjacency -> bitmask
    {
        const float4* ab = (const float4*)(adj + (size_t)bs_idx * 128 * 128);
#pragma unroll
        for (int ww = 0; ww < 2; ++ww) {
            int w = tid * 2 + ww, l = w >> 2, part = w & 3;
            const float4* pp = ab + (l * 128 + part * 32) / 4;
            unsigned m = 0;
#pragma unroll
            for (int q = 0; q < 8; ++q) {
                float4 v = pp[q];
                m |= (v.x > 0.5f) << (q * 4) | (v.y > 0.5f) << (q * 4 + 1)
                   | (v.z > 0.5f) << (q * 4 + 2) | (v.w > 0.5f) << (q * 4 + 3);
            }
            mask[w] = m;
        }
    }
    __syncthreads();
    if (tid < 128)
        degp[tid] = (float)(__popc(mask[tid*4]) + __popc(mask[tid*4+1]) +
                            __popc(mask[tid*4+2]) + __popc(mask[tid*4+3]));
    __syncthreads();

    float acc[64], gate[64];
    float dgv[4];
#pragma unroll
    for (int mi = 0; mi < 2; ++mi)
#pragma unroll
        for (int qr = 0; qr < 2; ++qr)
            dgv[mi * 2 + qr] = degp[trow0 + mi * 16 + qr * 8];

    for (int it = 0; it < NUM_LOOP; ++it) {
        const int p0 = it * 6;
        // s = A @ nf (reconstruct hi+lo; write single fp16 image)
        for (int r = 0; r < 16; ++r) {
            int l = warp * 16 + r;
            float a0 = 0.f, a1 = 0.f, a2 = 0.f, a3 = 0.f;
#pragma unroll
            for (int w4 = 0; w4 < 4; ++w4) {
                unsigned m = mask[l * 4 + w4];
                while (m) {
                    int c = w4 * 32 + __ffs((int)m) - 1; m &= m - 1;
                    uint32_t off = baddr(c, lane * 4);
                    uint2 vh = *(uint2*)(nfh + off), vl = *(uint2*)(nfl + off);
                    float2 h0 = upk2(vh.x), h1 = upk2(vh.y), l0 = upk2(vl.x), l1 = upk2(vl.y);
                    a0 += h0.x + l0.x; a1 += h0.y + l0.y; a2 += h1.x + l1.x; a3 += h1.y + l1.y;
                }
            }
            uint32_t off = baddr(l, lane * 4);
            *(uint2*)(shh + off) = make_uint2(pack_h2(a0, a1), pack_h2(a2, a3));
        }
        // ---- r = sigmoid(s@G_r + nf@Whh_r + deg*u + b) ----
#pragma unroll
        for (int i = 0; i < 64; ++i) acc[i] = 0.f;
        consume_part(p0+0, A_SH,  0, false, acc, sb32, tid, mrow, ncol, lane);
        consume_part(p0+1, A_NFH, 0, false, acc, sb32, tid, mrow, ncol, lane);
#pragma unroll
        for (int mi = 0; mi < 2; ++mi)
#pragma unroll
            for (int ni = 0; ni < 8; ++ni)
#pragma unroll
                for (int q = 0; q < 4; ++q) {
                    int idx = (mi*8+ni)*4+q, col = tcol0 + ni*8 + (q&1);
                    gate[idx] = fsig(acc[idx] + dgv[mi*2+(q>>1)]*sup[col] + bihp[col] + bhhp[col]);
                }
        // ---- n: acc = nf@Whh_n; gate *= (acc+bhh_n); acc = s@G_n; n = tanh(...) ----
#pragma unroll
        for (int i = 0; i < 64; ++i) acc[i] = 0.f;
        consume_part(p0+2, A_NFH, 0, false, acc, sb32, tid, mrow, ncol, lane);
#pragma unroll
        for (int mi = 0; mi < 2; ++mi)
#pragma unroll
            for (int ni = 0; ni < 8; ++ni)
#pragma unroll
                for (int q = 0; q < 4; ++q) {
                    int idx = (mi*8+ni)*4+q, col = tcol0 + ni*8 + (q&1);
                    gate[idx] *= (acc[idx] + bhhp[256 + col]);
                }
#pragma unroll
        for (int i = 0; i < 64; ++i) acc[i] = 0.f;
        consume_part(p0+3, A_SH, 0, false, acc, sb32, tid, mrow, ncol, lane);
#pragma unroll
        for (int mi = 0; mi < 2; ++mi)
#pragma unroll
            for (int ni = 0; ni < 8; ++ni)
#pragma unroll
                for (int q = 0; q < 4; ++q) {
                    int idx = (mi*8+ni)*4+q, col = tcol0 + ni*8 + (q&1);
                    gate[idx] = ftanh(acc[idx] + dgv[mi*2+(q>>1)]*sup[256+col] + bihp[256+col] + gate[idx]);
                }
        // ---- z + update: nf = n + z*(nf - n) ----
#pragma unroll
        for (int i = 0; i < 64; ++i) acc[i] = 0.f;
        consume_part(p0+4, A_SH,  0, false, acc, sb32, tid, mrow, ncol, lane);
        consume_part(p0+5, A_NFH, 0, false, acc, sb32, tid, mrow, ncol, lane);
#pragma unroll
        for (int mi = 0; mi < 2; ++mi)
#pragma unroll
            for (int ni = 0; ni < 8; ++ni)
#pragma unroll
                for (int qr = 0; qr < 2; ++qr) {
                    int row = trow0 + mi*16 + qr*8, colp = tcol0 + ni*8;
                    int i0 = (mi*8+ni)*4 + qr*2;
                    float dg = dgv[mi*2+qr];
                    float z0 = fsig(acc[i0]   + dg*sup[128+colp]   + bihp[128+colp]   + bhhp[128+colp]);
                    float z1 = fsig(acc[i0+1] + dg*sup[128+colp+1] + bihp[128+colp+1] + bhhp[128+colp+1]);
                    uint32_t off = baddr(row, colp);
                    float2 oh = upk2(*(uint32_t*)(nfh + off)), ol = upk2(*(uint32_t*)(nfl + off));
                    float o0 = oh.x + ol.x, o1 = oh.y + ol.y;
                    float n0 = gate[i0], n1 = gate[i0+1];
                    float w0 = n0 + z0 * (o0 - n0), w1 = n1 + z1 * (o1 - n1);
                    uint32_t lo, hi = pack_split(w0, w1, lo);
                    *(uint32_t*)(nfh + off) = hi;
                    *(uint32_t*)(nfl + off) = lo;
                }
        __syncthreads();   // nf ready for next gather / MLP
    }

    // ---- MLP (3-pass for output fidelity): h1 = tanh(nf@mW1^T + b1) ----
#pragma unroll
    for (int i = 0; i < 64; ++i) acc[i] = 0.f;
    consume_part(60, A_NFH, A_NFL, true,  acc, sb32, tid, mrow, ncol, lane);  // mW1 hi
    consume_part(61, A_NFH, 0,     false, acc, sb32, tid, mrow, ncol, lane);  // mW1 lo
#pragma unroll
    for (int mi = 0; mi < 2; ++mi)
#pragma unroll
        for (int ni = 0; ni < 8; ++ni)
#pragma unroll
            for (int qr = 0; qr < 2; ++qr) {
                int row = trow0 + mi*16 + qr*8, colp = tcol0 + ni*8;
                int i0 = (mi*8+ni)*4 + qr*2;
                float v0 = ftanh(acc[i0]   + mb1p[colp]);
                float v1 = ftanh(acc[i0+1] + mb1p[colp+1]);
                uint32_t lo, hi = pack_split(v0, v1, lo);
                uint32_t off = baddr(row, colp);
                *(uint32_t*)(shh + off) = hi;    // h1 hi
                *(uint32_t*)(nfl + off) = lo;    // h1 lo (nf dead now)
            }
#pragma unroll
    for (int i = 0; i < 64; ++i) acc[i] = 0.f;
    consume_part(62, A_SH, A_NFL, true,  acc, sb32, tid, mrow, ncol, lane);   // mW2 hi
    consume_part(63, A_SH, 0,     false, acc, sb32, tid, mrow, ncol, lane);   // mW2 lo
    {
        float rsum[4] = {0.f, 0.f, 0.f, 0.f};
#pragma unroll
        for (int mi = 0; mi < 2; ++mi)
#pragma unroll
            for (int ni = 0; ni < 8; ++ni)
#pragma unroll
                for (int q = 0; q < 4; ++q) {
                    int idx = (mi*8+ni)*4+q, col = tcol0 + ni*8 + (q&1);
                    rsum[mi*2+(q>>1)] += ftanh(acc[idx] + mb2p[col]) * w3p[col];
                }
#pragma unroll
        for (int k = 0; k < 4; ++k) {
            rsum[k] += __shfl_xor_sync(0xFFFFFFFFu, rsum[k], 1);
            rsum[k] += __shfl_xor_sync(0xFFFFFFFFu, rsum[k], 2);
        }
        if ((lane & 3) == 0) {
#pragma unroll
            for (int mi = 0; mi < 2; ++mi)
#pragma unroll
                for (int qr = 0; qr < 2; ++qr)
                    redp[warpN * 128 + trow0 + mi*16 + qr*8] = rsum[mi*2+qr];
        }
    }
    __syncthreads();
    if (tid < 128)
        out[bs_idx * 128 + tid] = ftanh(redp[tid] + redp[128 + tid] + mb3[0]);
}

extern "C" void kernel_launch(void* const* d_in, const int* in_sizes, int n_in,
                              void* d_out, int out_size) {
    const int*   input_var = (const int*)  d_in[0];
    const float* adjacency = (const float*)d_in[1];
    const float* emb       = (const float*)d_in[2];
    const float* gnn_w     = (const float*)d_in[3];
    const float* gnn_b     = (const float*)d_in[4];
    const float* W_ih      = (const float*)d_in[5];
    const float* W_hh      = (const float*)d_in[6];
    const float* b_ih      = (const float*)d_in[7];
    const float* b_hh      = (const float*)d_in[8];
    const float* mW1       = (const float*)d_in[9];
    const float* mb1       = (const float*)d_in[10];
    const float* mW2       = (const float*)d_in[11];
    const float* mb2       = (const float*)d_in[12];
    const float* mW3       = (const float*)d_in[13];
    const float* mb3       = (const float*)d_in[14];
    float* out = (float*)d_out;

    prep_g<<<192, 256>>>(gnn_w, W_ih, gnn_b);
    prep_w<<<320, 256>>>(W_hh, mW1, mW2);

    cudaFuncSetAttribute(gnn_main, cudaFuncAttributeMaxDynamicSharedMemorySize, SMEM_TOTAL);
    gnn_main<<<NBS, 256, SMEM_TOTAL>>>(input_var, adjacency, emb,
                                       b_ih, b_hh, mb1, mb2, mW3, mb3, out);
}

// round 16
// speedup vs baseline: 5.5497x; 1.2284x over previous
#include <cuda_runtime.h>
#include <cuda_fp16.h>
#include <stdint.h>

#define NBS 2048
#define NUM_LOOP 10

// smem byte offsets
#define OFF_NFH 0
#define OFF_NFL 32768
#define OFF_SH  65536
#define OFF_WB0 98304           /* three 32KB weight stage buffers */
#define OFF_MASK 196608
#define OFF_DEG  198656
#define OFF_SU   199168
#define OFF_BIH  200704
#define OFF_BHH  202240
#define OFF_MB1  203776
#define OFF_MB2  204288
#define OFF_W3   204800
#define OFF_RED  205312
#define OFF_COLS 206336         /* per-row column lists: 128 x 32 uint8 */
#define OFF_CNT  210432         /* 128 int */
#define SMEM_TOTAL 210944

// blocked SW128 fp16 tile addressing: atom 8 rows x 64 cols, atom_off = atom_row + atom_col*16
__host__ __device__ __forceinline__ uint32_t baddr(int row, int col) {
    uint32_t b = ((uint32_t)((row >> 3) + ((col >> 6) << 4)) << 10)
               | ((uint32_t)(row & 7) << 7) | ((uint32_t)(col & 63) << 1);
    return b ^ ((b >> 3) & 0x70);
}

// 8 weight tiles x {hi,lo} fp16, [out_n][in_k]: 0..2 G_r/z/n, 3..5 Whh_r/z/n, 6 mW1, 7 mW2
__device__ __align__(16) unsigned short g_w[8][2][128 * 128];
__device__ float g_u[384];

__device__ __forceinline__ void hsplit_store(float v, int tile, int h, int k) {
    __half hh = __float2half_rn(v);
    __half hl = __float2half_rn(v - __half2float(hh));
    uint32_t off = baddr(h, k);
    *(unsigned short*)((char*)g_w[tile][0] + off) = __half_as_ushort(hh);
    *(unsigned short*)((char*)g_w[tile][1] + off) = __half_as_ushort(hl);
}

__global__ void prep_g(const float* __restrict__ gnn_w, const float* __restrict__ W_ih,
                       const float* __restrict__ gnn_b) {
    int t = blockIdx.x * blockDim.x + threadIdx.x;
    if (t >= 3 * 16384) return;
    int gate = t >> 14, rem = t & 16383, h = rem >> 7, k = rem & 127;
    const float* a = W_ih + (gate * 128 + h) * 128;
    const float* b = gnn_w + k * 128;
    float acc = 0.f;
#pragma unroll 4
    for (int m = 0; m < 128; ++m) acc = fmaf(a[m], b[m], acc);
    hsplit_store(acc, gate, h, k);
    if (t < 384) {
        const float* a2 = W_ih + t * 128;
        float u = 0.f;
#pragma unroll 4
        for (int m = 0; m < 128; ++m) u = fmaf(gnn_b[m], a2[m], u);
        g_u[t] = u;
    }
}

__global__ void prep_w(const float* __restrict__ W_hh, const float* __restrict__ mW1,
                       const float* __restrict__ mW2) {
    int t = blockIdx.x * blockDim.x + threadIdx.x;
    if (t >= 5 * 16384) return;
    int rem = t & 16383, h = rem >> 7, k = rem & 127;
    float v; int tile;
    if (t < 3 * 16384)      { tile = 3 + (t >> 14); v = W_hh[((t >> 14) * 128 + h) * 128 + k]; }
    else if (t < 4 * 16384) { tile = 6; v = mW1[h * 128 + k]; }
    else                    { tile = 7; v = mW2[h * 128 + k]; }
    hsplit_store(v, tile, h, k);
}

// ---- helpers ----
__device__ __forceinline__ uint32_t smem_u32(const void* p) {
    uint32_t a;
    asm("{ .reg .u64 t; cvta.to.shared.u64 t, %1; cvt.u32.u64 %0, t; }" : "=r"(a) : "l"(p));
    return a;
}
__device__ __forceinline__ float fsig(float x) { return __fdividef(1.0f, 1.0f + __expf(-x)); }
__device__ __forceinline__ float ftanh(float x) { return 1.0f - __fdividef(2.0f, __expf(2.0f * x) + 1.0f); }
__device__ __forceinline__ float tanha(float x) {
    float y; asm("tanh.approx.f32 %0, %1;" : "=f"(y) : "f"(x)); return y;
}
__device__ __forceinline__ float fsiga(float x) { return fmaf(0.5f, tanha(0.5f * x), 0.5f); }
__device__ __forceinline__ uint32_t pack_split(float v0, float v1, uint32_t& lo) {
    __half h0 = __float2half_rn(v0), h1 = __float2half_rn(v1);
    __half l0 = __float2half_rn(v0 - __half2float(h0));
    __half l1 = __float2half_rn(v1 - __half2float(h1));
    lo = (uint32_t)__half_as_ushort(l0) | ((uint32_t)__half_as_ushort(l1) << 16);
    return (uint32_t)__half_as_ushort(h0) | ((uint32_t)__half_as_ushort(h1) << 16);
}
__device__ __forceinline__ uint32_t pack_h2(float v0, float v1) {
    __half2 h = __floats2half2_rn(v0, v1);
    return *reinterpret_cast<uint32_t*>(&h);
}
__device__ __forceinline__ float2 upk2(uint32_t w) {
    __half2 h = *reinterpret_cast<__half2*>(&w);
    return __half22float2(h);
}
__device__ __forceinline__ void ldsm4(uint32_t* r, uint32_t addr) {
    asm volatile("ldmatrix.sync.aligned.m8n8.x4.shared.b16 {%0,%1,%2,%3}, [%4];"
        : "=r"(r[0]), "=r"(r[1]), "=r"(r[2]), "=r"(r[3]) : "r"(addr));
}
__device__ __forceinline__ void mma16816(float* d, const uint32_t* a, const uint32_t* b) {
    asm volatile("mma.sync.aligned.m16n8k16.row.col.f32.f16.f16.f32 "
        "{%0,%1,%2,%3}, {%4,%5,%6,%7}, {%8,%9}, {%0,%1,%2,%3};"
        : "+f"(d[0]), "+f"(d[1]), "+f"(d[2]), "+f"(d[3])
        : "r"(a[0]), "r"(a[1]), "r"(a[2]), "r"(a[3]), "r"(b[0]), "r"(b[1]));
}

__device__ __forceinline__ void lda_ks(uint32_t Ab, int ks, int mrow, int lane, uint32_t a[2][4]) {
    int k0 = ks * 16;
#pragma unroll
    for (int mi = 0; mi < 2; ++mi) {
        int row = mrow + mi * 16 + (lane & 15);
        int col = k0 + ((lane >> 4) << 3);
        ldsm4(a[mi], Ab + baddr(row, col));
    }
}
__device__ __forceinline__ void ldb_ks(uint32_t Bb, int ks, int ncol, int lane, uint32_t b[8][2]) {
    int k0 = ks * 16;
#pragma unroll
    for (int np = 0; np < 4; ++np) {
        uint32_t t[4];
        int nrow = ncol + np * 16 + (lane & 7) + ((lane >> 4) << 3);
        int col  = k0 + (((lane >> 3) & 1) << 3);
        ldsm4(t, Bb + baddr(nrow, col));
        b[np*2][0] = t[0]; b[np*2][1] = t[1];
        b[np*2+1][0] = t[2]; b[np*2+1][1] = t[3];
    }
}

// pipelined gemm pass: acc(32m x 64n warp tile) += A[128x128 @Ab] @ B[128x128 @Bb]^T
__device__ __forceinline__ void mma_pass(uint32_t Ab, uint32_t Bb, float* acc,
                                         int mrow, int ncol, int lane) {
    uint32_t a[2][2][4], b[2][8][2];
    lda_ks(Ab, 0, mrow, lane, a[0]);
    ldb_ks(Bb, 0, ncol, lane, b[0]);
#pragma unroll
    for (int ks = 0; ks < 8; ++ks) {
        int cu = ks & 1;
        if (ks < 7) {                      // prefetch next k-step under the MMAs
            lda_ks(Ab, ks + 1, mrow, lane, a[cu ^ 1]);
            ldb_ks(Bb, ks + 1, ncol, lane, b[cu ^ 1]);
        }
#pragma unroll
        for (int mi = 0; mi < 2; ++mi)
#pragma unroll
            for (int ni = 0; ni < 8; ++ni)
                mma16816(acc + (mi * 8 + ni) * 4, a[cu][mi], b[cu][ni]);
    }
}

// weight staging: parts 0..63. Per-iter 6 parts (GRU, hi images only) then 4 MLP parts (hi+lo).
#define LAST_PART 63
__device__ __forceinline__ void issue_part(int p, uint32_t sb32, int tid) {
    if (p > LAST_PART) return;
    int tile, sel;
    if (p < 60) { const int PT6[6] = {0, 3, 5, 2, 1, 4}; tile = PT6[p % 6]; sel = 0; }
    else        { const int MT[4] = {6, 6, 7, 7}; tile = MT[p - 60]; sel = (p - 60) & 1; }
    const char* src = (const char*)g_w[tile][sel];
    uint32_t dst = sb32 + OFF_WB0 + (uint32_t)(p % 3) * 32768u;
#pragma unroll
    for (int q = 0; q < 8; ++q) {
        uint32_t off = (uint32_t)(q * 256 + tid) * 16u;
        asm volatile("cp.async.cg.shared.global [%0], [%1], 16;"
                     :: "r"(dst + off), "l"(src + off) : "memory");
    }
    asm volatile("cp.async.commit_group;" ::: "memory");
}
__device__ __forceinline__ void consume_part(int p, uint32_t Ah, uint32_t Al, bool two,
                                             float* acc, uint32_t sb32, int tid,
                                             int mrow, int ncol, int lane) {
    if (p < LAST_PART) asm volatile("cp.async.wait_group 1;" ::: "memory");
    else               asm volatile("cp.async.wait_group 0;" ::: "memory");
    __syncthreads();
    issue_part(p + 2, sb32, tid);
    uint32_t B = sb32 + OFF_WB0 + (uint32_t)(p % 3) * 32768u;
    mma_pass(Ah, B, acc, mrow, ncol, lane);
    if (two) mma_pass(Al, B, acc, mrow, ncol, lane);
}

__global__ void __launch_bounds__(256, 1)
gnn_main(const int* __restrict__ input_var, const float* __restrict__ adj,
         const float* __restrict__ emb, const float* __restrict__ b_ih,
         const float* __restrict__ b_hh, const float* __restrict__ mb1,
         const float* __restrict__ mb2, const float* __restrict__ mW3,
         const float* __restrict__ mb3, float* __restrict__ out) {
    extern __shared__ char sm[];
    const uint32_t sb32 = smem_u32(sm);
    const int tid = threadIdx.x, lane = tid & 31, warp = tid >> 5;
    const int bs_idx = blockIdx.x;
    char* nfh = sm + OFF_NFH; char* nfl = sm + OFF_NFL;
    char* shh = sm + OFF_SH;
    unsigned* mask = (unsigned*)(sm + OFF_MASK);
    float* degp = (float*)(sm + OFF_DEG);
    float* sup  = (float*)(sm + OFF_SU);
    float* bihp = (float*)(sm + OFF_BIH);
    float* bhhp = (float*)(sm + OFF_BHH);
    float* mb1p = (float*)(sm + OFF_MB1);
    float* mb2p = (float*)(sm + OFF_MB2);
    float* w3p  = (float*)(sm + OFF_W3);
    float* redp = (float*)(sm + OFF_RED);
    uint8_t* colb = (uint8_t*)(sm + OFF_COLS);
    int* cntp = (int*)(sm + OFF_CNT);

    const int warpM = warp >> 1, warpN = warp & 1;
    const int mrow = warpM * 32, ncol = warpN * 64;
    const int trow0 = mrow + (lane >> 2);
    const int tcol0 = ncol + ((lane & 3) << 1);
    const uint32_t A_NFH = sb32 + OFF_NFH, A_NFL = sb32 + OFF_NFL;
    const uint32_t A_SH  = sb32 + OFF_SH;

    issue_part(0, sb32, tid);
    issue_part(1, sb32, tid);

    for (int t = tid; t < 384; t += 256) { sup[t] = g_u[t]; bihp[t] = b_ih[t]; bhhp[t] = b_hh[t]; }
    if (tid < 128) { mb1p[tid] = mb1[tid]; mb2p[tid] = mb2[tid]; w3p[tid] = mW3[tid]; }

    // embedding gather -> nf hi/lo split (state at ~2^-22; MMA reads hi image)
    {
        const int* iv = input_var + bs_idx * 128;
        for (int r = 0; r < 16; ++r) {
            int l = warp * 16 + r;
            float4 v = ((const float4*)(emb + (size_t)iv[l] * 128))[lane];
            uint32_t lo0, lo1, hi0 = pack_split(v.x, v.y, lo0), hi1 = pack_split(v.z, v.w, lo1);
            uint32_t off = baddr(l, lane * 4);
            *(uint2*)(nfh + off) = make_uint2(hi0, hi1);
            *(uint2*)(nfl + off) = make_uint2(lo0, lo1);
        }
    }
    // adjacency -> bitmask
    {
        const float4* ab = (const float4*)(adj + (size_t)bs_idx * 128 * 128);
#pragma unroll
        for (int ww = 0; ww < 2; ++ww) {
            int w = tid * 2 + ww, l = w >> 2, part = w & 3;
            const float4* pp = ab + (l * 128 + part * 32) / 4;
            unsigned m = 0;
#pragma unroll
            for (int q = 0; q < 8; ++q) {
                float4 v = pp[q];
                m |= (v.x > 0.5f) << (q * 4) | (v.y > 0.5f) << (q * 4 + 1)
                   | (v.z > 0.5f) << (q * 4 + 2) | (v.w > 0.5f) << (q * 4 + 3);
            }
            mask[w] = m;
        }
    }
    __syncthreads();
    // mask is loop-invariant: expand to per-row column index lists ONCE
    if (tid < 128) {
        uint8_t* cl = colb + tid * 32;
        int cnt = 0;
#pragma unroll
        for (int w4 = 0; w4 < 4; ++w4) {
            unsigned m = mask[tid * 4 + w4];
            while (m && cnt < 32) {
                int c = w4 * 32 + __ffs((int)m) - 1; m &= m - 1;
                cl[cnt++] = (uint8_t)c;
            }
        }
        cntp[tid] = cnt;
        degp[tid] = (float)cnt;
    }
    __syncthreads();

    float acc[64], gate[64];
    float dgv[4];
#pragma unroll
    for (int mi = 0; mi < 2; ++mi)
#pragma unroll
        for (int qr = 0; qr < 2; ++qr)
            dgv[mi * 2 + qr] = degp[trow0 + mi * 16 + qr * 8];

    for (int it = 0; it < NUM_LOOP; ++it) {
        const int p0 = it * 6;
        // s = A @ nf via column lists; hi image only (s is fp16-rounded anyway)
        for (int r = 0; r < 16; ++r) {
            int l = warp * 16 + r;
            const uint8_t* cl = colb + l * 32;
            int cnt = cntp[l];
            float a0 = 0.f, a1 = 0.f, a2 = 0.f, a3 = 0.f;
            for (int j = 0; j < cnt; ++j) {
                int c = cl[j];
                uint2 vh = *(uint2*)(nfh + baddr(c, lane * 4));
                float2 h0 = upk2(vh.x), h1 = upk2(vh.y);
                a0 += h0.x; a1 += h0.y; a2 += h1.x; a3 += h1.y;
            }
            uint32_t off = baddr(l, lane * 4);
            *(uint2*)(shh + off) = make_uint2(pack_h2(a0, a1), pack_h2(a2, a3));
        }
        // ---- r = sigmoid(s@G_r + nf@Whh_r + deg*u + b)  [tanh.approx] ----
#pragma unroll
        for (int i = 0; i < 64; ++i) acc[i] = 0.f;
        consume_part(p0+0, A_SH,  0, false, acc, sb32, tid, mrow, ncol, lane);
        consume_part(p0+1, A_NFH, 0, false, acc, sb32, tid, mrow, ncol, lane);
#pragma unroll
        for (int mi = 0; mi < 2; ++mi)
#pragma unroll
            for (int ni = 0; ni < 8; ++ni)
#pragma unroll
                for (int q = 0; q < 4; ++q) {
                    int idx = (mi*8+ni)*4+q, col = tcol0 + ni*8 + (q&1);
                    gate[idx] = fsiga(acc[idx] + dgv[mi*2+(q>>1)]*sup[col] + bihp[col] + bhhp[col]);
                }
        // ---- n: acc = nf@Whh_n; gate *= (acc+bhh_n); acc = s@G_n; n = tanh.approx(...) ----
#pragma unroll
        for (int i = 0; i < 64; ++i) acc[i] = 0.f;
        consume_part(p0+2, A_NFH, 0, false, acc, sb32, tid, mrow, ncol, lane);
#pragma unroll
        for (int mi = 0; mi < 2; ++mi)
#pragma unroll
            for (int ni = 0; ni < 8; ++ni)
#pragma unroll
                for (int q = 0; q < 4; ++q) {
                    int idx = (mi*8+ni)*4+q, col = tcol0 + ni*8 + (q&1);
                    gate[idx] *= (acc[idx] + bhhp[256 + col]);
                }
#pragma unroll
        for (int i = 0; i < 64; ++i) acc[i] = 0.f;
        consume_part(p0+3, A_SH, 0, false, acc, sb32, tid, mrow, ncol, lane);
#pragma unroll
        for (int mi = 0; mi < 2; ++mi)
#pragma unroll
            for (int ni = 0; ni < 8; ++ni)
#pragma unroll
                for (int q = 0; q < 4; ++q) {
                    int idx = (mi*8+ni)*4+q, col = tcol0 + ni*8 + (q&1);
                    gate[idx] = tanha(acc[idx] + dgv[mi*2+(q>>1)]*sup[256+col] + bihp[256+col] + gate[idx]);
                }
        // ---- z + update (z kept PRECISE: it mixes the state) ----
#pragma unroll
        for (int i = 0; i < 64; ++i) acc[i] = 0.f;
        consume_part(p0+4, A_SH,  0, false, acc, sb32, tid, mrow, ncol, lane);
        consume_part(p0+5, A_NFH, 0, false, acc, sb32, tid, mrow, ncol, lane);
#pragma unroll
        for (int mi = 0; mi < 2; ++mi)
#pragma unroll
            for (int ni = 0; ni < 8; ++ni)
#pragma unroll
                for (int qr = 0; qr < 2; ++qr) {
                    int row = trow0 + mi*16 + qr*8, colp = tcol0 + ni*8;
                    int i0 = (mi*8+ni)*4 + qr*2;
                    float dg = dgv[mi*2+qr];
                    float z0 = fsig(acc[i0]   + dg*sup[128+colp]   + bihp[128+colp]   + bhhp[128+colp]);
                    float z1 = fsig(acc[i0+1] + dg*sup[128+colp+1] + bihp[128+colp+1] + bhhp[128+colp+1]);
                    uint32_t off = baddr(row, colp);
                    float2 oh = upk2(*(uint32_t*)(nfh + off)), ol = upk2(*(uint32_t*)(nfl + off));
                    float o0 = oh.x + ol.x, o1 = oh.y + ol.y;
                    float n0 = gate[i0], n1 = gate[i0+1];
                    float w0 = n0 + z0 * (o0 - n0), w1 = n1 + z1 * (o1 - n1);
                    uint32_t lo, hi = pack_split(w0, w1, lo);
                    *(uint32_t*)(nfh + off) = hi;
                    *(uint32_t*)(nfl + off) = lo;
                }
        __syncthreads();   // nf ready for next gather / MLP
    }

    // ---- MLP (3-pass, precise activations): h1 = tanh(nf@mW1^T + b1) ----
#pragma unroll
    for (int i = 0; i < 64; ++i) acc[i] = 0.f;
    consume_part(60, A_NFH, A_NFL, true,  acc, sb32, tid, mrow, ncol, lane);  // mW1 hi
    consume_part(61, A_NFH, 0,     false, acc, sb32, tid, mrow, ncol, lane);  // mW1 lo
#pragma unroll
    for (int mi = 0; mi < 2; ++mi)
#pragma unroll
        for (int ni = 0; ni < 8; ++ni)
#pragma unroll
            for (int qr = 0; qr < 2; ++qr) {
                int row = trow0 + mi*16 + qr*8, colp = tcol0 + ni*8;
                int i0 = (mi*8+ni)*4 + qr*2;
                float v0 = ftanh(acc[i0]   + mb1p[colp]);
                float v1 = ftanh(acc[i0+1] + mb1p[colp+1]);
                uint32_t lo, hi = pack_split(v0, v1, lo);
                uint32_t off = baddr(row, colp);
                *(uint32_t*)(shh + off) = hi;    // h1 hi
                *(uint32_t*)(nfl + off) = lo;    // h1 lo (nf dead now)
            }
#pragma unroll
    for (int i = 0; i < 64; ++i) acc[i] = 0.f;
    consume_part(62, A_SH, A_NFL, true,  acc, sb32, tid, mrow, ncol, lane);   // mW2 hi
    consume_part(63, A_SH, 0,     false, acc, sb32, tid, mrow, ncol, lane);   // mW2 lo
    {
        float rsum[4] = {0.f, 0.f, 0.f, 0.f};
#pragma unroll
        for (int mi = 0; mi < 2; ++mi)
#pragma unroll
            for (int ni = 0; ni < 8; ++ni)
#pragma unroll
                for (int q = 0; q < 4; ++q) {
                    int idx = (mi*8+ni)*4+q, col = tcol0 + ni*8 + (q&1);
                    rsum[mi*2+(q>>1)] += ftanh(acc[idx] + mb2p[col]) * w3p[col];
                }
#pragma unroll
        for (int k = 0; k < 4; ++k) {
            rsum[k] += __shfl_xor_sync(0xFFFFFFFFu, rsum[k], 1);
            rsum[k] += __shfl_xor_sync(0xFFFFFFFFu, rsum[k], 2);
        }
        if ((lane & 3) == 0) {
#pragma unroll
            for (int mi = 0; mi < 2; ++mi)
#pragma unroll
                for (int qr = 0; qr < 2; ++qr)
                    redp[warpN * 128 + trow0 + mi*16 + qr*8] = rsum[mi*2+qr];
        }
    }
    __syncthreads();
    if (tid < 128)
        out[bs_idx * 128 + tid] = ftanh(redp[tid] + redp[128 + tid] + mb3[0]);
}

extern "C" void kernel_launch(void* const* d_in, const int* in_sizes, int n_in,
                              void* d_out, int out_size) {
    const int*   input_var = (const int*)  d_in[0];
    const float* adjacency = (const float*)d_in[1];
    const float* emb       = (const float*)d_in[2];
    const float* gnn_w     = (const float*)d_in[3];
    const float* gnn_b     = (const float*)d_in[4];
    const float* W_ih      = (const float*)d_in[5];
    const float* W_hh      = (const float*)d_in[6];
    const float* b_ih      = (const float*)d_in[7];
    const float* b_hh      = (const float*)d_in[8];
    const float* mW1       = (const float*)d_in[9];
    const float* mb1       = (const float*)d_in[10];
    const float* mW2       = (const float*)d_in[11];
    const float* mb2       = (const float*)d_in[12];
    const float* mW3       = (const float*)d_in[13];
    const float* mb3       = (const float*)d_in[14];
    float* out = (float*)d_out;

    prep_g<<<192, 256>>>(gnn_w, W_ih, gnn_b);
    prep_w<<<320, 256>>>(W_hh, mW1, mW2);

    cudaFuncSetAttribute(gnn_main, cudaFuncAttributeMaxDynamicSharedMemorySize, SMEM_TOTAL);
    gnn_main<<<NBS, 256, SMEM_TOTAL>>>(input_var, adjacency, emb,
                                       b_ih, b_hh, mb1, mb2, mW3, mb3, out);
}

// round 17
// speedup vs baseline: 5.6441x; 1.0170x over previous
#include <cuda_runtime.h>
#include <cuda_fp16.h>
#include <stdint.h>

#define NBS 2048
#define NUM_LOOP 10

// smem byte offsets
#define OFF_NFH 0
#define OFF_NFL 32768
#define OFF_SH  65536
#define OFF_WB0 98304           /* three 32KB weight stage buffers */
#define OFF_MASK 196608
#define OFF_DEG  198656
#define OFF_SU   199168
#define OFF_BIH  200704
#define OFF_BHH  202240
#define OFF_MB1  203776
#define OFF_MB2  204288
#define OFF_W3   204800
#define OFF_RED  205312
#define OFF_COLS 206336         /* per-row column lists: 128 x 32 uint8 */
#define OFF_CNT  210432         /* 128 int */
#define SMEM_TOTAL 210944

// blocked SW128 fp16 tile addressing: atom 8 rows x 64 cols, atom_off = atom_row + atom_col*16
__host__ __device__ __forceinline__ uint32_t baddr(int row, int col) {
    uint32_t b = ((uint32_t)((row >> 3) + ((col >> 6) << 4)) << 10)
               | ((uint32_t)(row & 7) << 7) | ((uint32_t)(col & 63) << 1);
    return b ^ ((b >> 3) & 0x70);
}

// 8 weight tiles x {hi,lo} fp16, [out_n][in_k]: 0..2 G_r/z/n, 3..5 Whh_r/z/n, 6 mW1, 7 mW2
__device__ __align__(16) unsigned short g_w[8][2][128 * 128];
__device__ float g_u[384];

__device__ __forceinline__ void hsplit_store(float v, int tile, int h, int k) {
    __half hh = __float2half_rn(v);
    __half hl = __float2half_rn(v - __half2float(hh));
    uint32_t off = baddr(h, k);
    *(unsigned short*)((char*)g_w[tile][0] + off) = __half_as_ushort(hh);
    *(unsigned short*)((char*)g_w[tile][1] + off) = __half_as_ushort(hl);
}

__global__ void prep_g(const float* __restrict__ gnn_w, const float* __restrict__ W_ih,
                       const float* __restrict__ gnn_b) {
    int t = blockIdx.x * blockDim.x + threadIdx.x;
    if (t >= 3 * 16384) return;
    int gate = t >> 14, rem = t & 16383, h = rem >> 7, k = rem & 127;
    const float* a = W_ih + (gate * 128 + h) * 128;
    const float* b = gnn_w + k * 128;
    // 4 independent FMA chains + float4 loads: latency-friendly (MLP ~16)
    float s0 = 0.f, s1 = 0.f, s2 = 0.f, s3 = 0.f;
#pragma unroll 8
    for (int m = 0; m < 128; m += 4) {
        float4 av = *(const float4*)(a + m);
        float4 bv = *(const float4*)(b + m);
        s0 = fmaf(av.x, bv.x, s0); s1 = fmaf(av.y, bv.y, s1);
        s2 = fmaf(av.z, bv.z, s2); s3 = fmaf(av.w, bv.w, s3);
    }
    hsplit_store((s0 + s1) + (s2 + s3), gate, h, k);
    if (t < 384) {
        const float* a2 = W_ih + t * 128;
        float u0 = 0.f, u1 = 0.f, u2 = 0.f, u3 = 0.f;
#pragma unroll 8
        for (int m = 0; m < 128; m += 4) {
            float4 av = *(const float4*)(a2 + m);
            float4 gv = *(const float4*)(gnn_b + m);
            u0 = fmaf(gv.x, av.x, u0); u1 = fmaf(gv.y, av.y, u1);
            u2 = fmaf(gv.z, av.z, u2); u3 = fmaf(gv.w, av.w, u3);
        }
        g_u[t] = (u0 + u1) + (u2 + u3);
    }
}

__global__ void prep_w(const float* __restrict__ W_hh, const float* __restrict__ mW1,
                       const float* __restrict__ mW2) {
    int t = blockIdx.x * blockDim.x + threadIdx.x;
    if (t >= 5 * 16384) return;
    int rem = t & 16383, h = rem >> 7, k = rem & 127;
    float v; int tile;
    if (t < 3 * 16384)      { tile = 3 + (t >> 14); v = W_hh[((t >> 14) * 128 + h) * 128 + k]; }
    else if (t < 4 * 16384) { tile = 6; v = mW1[h * 128 + k]; }
    else                    { tile = 7; v = mW2[h * 128 + k]; }
    hsplit_store(v, tile, h, k);
}

// ---- helpers ----
__device__ __forceinline__ uint32_t smem_u32(const void* p) {
    uint32_t a;
    asm("{ .reg .u64 t; cvta.to.shared.u64 t, %1; cvt.u32.u64 %0, t; }" : "=r"(a) : "l"(p));
    return a;
}
__device__ __forceinline__ float ftanh(float x) { return 1.0f - __fdividef(2.0f, __expf(2.0f * x) + 1.0f); }
__device__ __forceinline__ float tanha(float x) {
    float y; asm("tanh.approx.f32 %0, %1;" : "=f"(y) : "f"(x)); return y;
}
__device__ __forceinline__ float fsiga(float x) { return fmaf(0.5f, tanha(0.5f * x), 0.5f); }
__device__ __forceinline__ uint32_t pack_split(float v0, float v1, uint32_t& lo) {
    __half h0 = __float2half_rn(v0), h1 = __float2half_rn(v1);
    __half l0 = __float2half_rn(v0 - __half2float(h0));
    __half l1 = __float2half_rn(v1 - __half2float(h1));
    lo = (uint32_t)__half_as_ushort(l0) | ((uint32_t)__half_as_ushort(l1) << 16);
    return (uint32_t)__half_as_ushort(h0) | ((uint32_t)__half_as_ushort(h1) << 16);
}
__device__ __forceinline__ uint32_t pack_h2(float v0, float v1) {
    __half2 h = __floats2half2_rn(v0, v1);
    return *reinterpret_cast<uint32_t*>(&h);
}
__device__ __forceinline__ float2 upk2(uint32_t w) {
    __half2 h = *reinterpret_cast<__half2*>(&w);
    return __half22float2(h);
}
__device__ __forceinline__ void ldsm4(uint32_t* r, uint32_t addr) {
    asm volatile("ldmatrix.sync.aligned.m8n8.x4.shared.b16 {%0,%1,%2,%3}, [%4];"
        : "=r"(r[0]), "=r"(r[1]), "=r"(r[2]), "=r"(r[3]) : "r"(addr));
}
__device__ __forceinline__ void mma16816(float* d, const uint32_t* a, const uint32_t* b) {
    asm volatile("mma.sync.aligned.m16n8k16.row.col.f32.f16.f16.f32 "
        "{%0,%1,%2,%3}, {%4,%5,%6,%7}, {%8,%9}, {%0,%1,%2,%3};"
        : "+f"(d[0]), "+f"(d[1]), "+f"(d[2]), "+f"(d[3])
        : "r"(a[0]), "r"(a[1]), "r"(a[2]), "r"(a[3]), "r"(b[0]), "r"(b[1]));
}

__device__ __forceinline__ void lda_ks(uint32_t Ab, int ks, int mrow, int lane, uint32_t a[2][4]) {
    int k0 = ks * 16;
#pragma unroll
    for (int mi = 0; mi < 2; ++mi) {
        int row = mrow + mi * 16 + (lane & 15);
        int col = k0 + ((lane >> 4) << 3);
        ldsm4(a[mi], Ab + baddr(row, col));
    }
}
__device__ __forceinline__ void ldb_ks(uint32_t Bb, int ks, int ncol, int lane, uint32_t b[8][2]) {
    int k0 = ks * 16;
#pragma unroll
    for (int np = 0; np < 4; ++np) {
        uint32_t t[4];
        int nrow = ncol + np * 16 + (lane & 7) + ((lane >> 4) << 3);
        int col  = k0 + (((lane >> 3) & 1) << 3);
        ldsm4(t, Bb + baddr(nrow, col));
        b[np*2][0] = t[0]; b[np*2][1] = t[1];
        b[np*2+1][0] = t[2]; b[np*2+1][1] = t[3];
    }
}

// pipelined gemm pass: acc(32m x 64n warp tile) += A[128x128 @Ab] @ B[128x128 @Bb]^T
__device__ __forceinline__ void mma_pass(uint32_t Ab, uint32_t Bb, float* acc,
                                         int mrow, int ncol, int lane) {
    uint32_t a[2][2][4], b[2][8][2];
    lda_ks(Ab, 0, mrow, lane, a[0]);
    ldb_ks(Bb, 0, ncol, lane, b[0]);
#pragma unroll
    for (int ks = 0; ks < 8; ++ks) {
        int cu = ks & 1;
        if (ks < 7) {                      // prefetch next k-step under the MMAs
            lda_ks(Ab, ks + 1, mrow, lane, a[cu ^ 1]);
            ldb_ks(Bb, ks + 1, ncol, lane, b[cu ^ 1]);
        }
#pragma unroll
        for (int mi = 0; mi < 2; ++mi)
#pragma unroll
            for (int ni = 0; ni < 8; ++ni)
                mma16816(acc + (mi * 8 + ni) * 4, a[cu][mi], b[cu][ni]);
    }
}

// weight staging: parts 0..63. Per-iter 6 parts (GRU, hi images only) then 4 MLP parts (hi+lo).
#define LAST_PART 63
__device__ __forceinline__ void issue_part(int p, uint32_t sb32, int tid) {
    if (p > LAST_PART) return;
    int tile, sel;
    if (p < 60) { const int PT6[6] = {0, 3, 5, 2, 1, 4}; tile = PT6[p % 6]; sel = 0; }
    else        { const int MT[4] = {6, 6, 7, 7}; tile = MT[p - 60]; sel = (p - 60) & 1; }
    const char* src = (const char*)g_w[tile][sel];
    uint32_t dst = sb32 + OFF_WB0 + (uint32_t)(p % 3) * 32768u;
#pragma unroll
    for (int q = 0; q < 8; ++q) {
        uint32_t off = (uint32_t)(q * 256 + tid) * 16u;
        asm volatile("cp.async.cg.shared.global [%0], [%1], 16;"
                     :: "r"(dst + off), "l"(src + off) : "memory");
    }
    asm volatile("cp.async.commit_group;" ::: "memory");
}
__device__ __forceinline__ void consume_part(int p, uint32_t Ah, uint32_t Al, bool two,
                                             float* acc, uint32_t sb32, int tid,
                                             int mrow, int ncol, int lane) {
    if (p < LAST_PART) asm volatile("cp.async.wait_group 1;" ::: "memory");
    else               asm volatile("cp.async.wait_group 0;" ::: "memory");
    __syncthreads();
    issue_part(p + 2, sb32, tid);
    uint32_t B = sb32 + OFF_WB0 + (uint32_t)(p % 3) * 32768u;
    mma_pass(Ah, B, acc, mrow, ncol, lane);
    if (two) mma_pass(Al, B, acc, mrow, ncol, lane);
}

__global__ void __launch_bounds__(256, 1)
gnn_main(const int* __restrict__ input_var, const float* __restrict__ adj,
         const float* __restrict__ emb, const float* __restrict__ b_ih,
         const float* __restrict__ b_hh, const float* __restrict__ mb1,
         const float* __restrict__ mb2, const float* __restrict__ mW3,
         const float* __restrict__ mb3, float* __restrict__ out) {
    extern __shared__ char sm[];
    const uint32_t sb32 = smem_u32(sm);
    const int tid = threadIdx.x, lane = tid & 31, warp = tid >> 5;
    const int bs_idx = blockIdx.x;
    char* nfh = sm + OFF_NFH; char* nfl = sm + OFF_NFL;
    char* shh = sm + OFF_SH;
    unsigned* mask = (unsigned*)(sm + OFF_MASK);
    float* degp = (float*)(sm + OFF_DEG);
    float* sup  = (float*)(sm + OFF_SU);
    float* bihp = (float*)(sm + OFF_BIH);
    float* bhhp = (float*)(sm + OFF_BHH);
    float* mb1p = (float*)(sm + OFF_MB1);
    float* mb2p = (float*)(sm + OFF_MB2);
    float* w3p  = (float*)(sm + OFF_W3);
    float* redp = (float*)(sm + OFF_RED);
    uint8_t* colb = (uint8_t*)(sm + OFF_COLS);
    int* cntp = (int*)(sm + OFF_CNT);

    const int warpM = warp >> 1, warpN = warp & 1;
    const int mrow = warpM * 32, ncol = warpN * 64;
    const int trow0 = mrow + (lane >> 2);
    const int tcol0 = ncol + ((lane & 3) << 1);
    const uint32_t A_NFH = sb32 + OFF_NFH, A_NFL = sb32 + OFF_NFL;
    const uint32_t A_SH  = sb32 + OFF_SH;

    issue_part(0, sb32, tid);
    issue_part(1, sb32, tid);

    for (int t = tid; t < 384; t += 256) { sup[t] = g_u[t]; bihp[t] = b_ih[t]; bhhp[t] = b_hh[t]; }
    if (tid < 128) { mb1p[tid] = mb1[tid]; mb2p[tid] = mb2[tid]; w3p[tid] = mW3[tid]; }

    // embedding gather -> nf hi/lo split (state at ~2^-22; MMA reads hi image)
    {
        const int* iv = input_var + bs_idx * 128;
        for (int r = 0; r < 16; ++r) {
            int l = warp * 16 + r;
            float4 v = ((const float4*)(emb + (size_t)iv[l] * 128))[lane];
            uint32_t lo0, lo1, hi0 = pack_split(v.x, v.y, lo0), hi1 = pack_split(v.z, v.w, lo1);
            uint32_t off = baddr(l, lane * 4);
            *(uint2*)(nfh + off) = make_uint2(hi0, hi1);
            *(uint2*)(nfl + off) = make_uint2(lo0, lo1);
        }
    }
    // adjacency -> bitmask
    {
        const float4* ab = (const float4*)(adj + (size_t)bs_idx * 128 * 128);
#pragma unroll
        for (int ww = 0; ww < 2; ++ww) {
            int w = tid * 2 + ww, l = w >> 2, part = w & 3;
            const float4* pp = ab + (l * 128 + part * 32) / 4;
            unsigned m = 0;
#pragma unroll
            for (int q = 0; q < 8; ++q) {
                float4 v = pp[q];
                m |= (v.x > 0.5f) << (q * 4) | (v.y > 0.5f) << (q * 4 + 1)
                   | (v.z > 0.5f) << (q * 4 + 2) | (v.w > 0.5f) << (q * 4 + 3);
            }
            mask[w] = m;
        }
    }
    __syncthreads();
    // mask is loop-invariant: expand to per-row column index lists ONCE
    if (tid < 128) {
        uint8_t* cl = colb + tid * 32;
        int cnt = 0;
#pragma unroll
        for (int w4 = 0; w4 < 4; ++w4) {
            unsigned m = mask[tid * 4 + w4];
            while (m && cnt < 32) {
                int c = w4 * 32 + __ffs((int)m) - 1; m &= m - 1;
                cl[cnt++] = (uint8_t)c;
            }
        }
        cntp[tid] = cnt;
        degp[tid] = (float)cnt;
    }
    __syncthreads();

    float acc[64], gate[64];
    float dgv[4];
#pragma unroll
    for (int mi = 0; mi < 2; ++mi)
#pragma unroll
        for (int qr = 0; qr < 2; ++qr)
            dgv[mi * 2 + qr] = degp[trow0 + mi * 16 + qr * 8];

    for (int it = 0; it < NUM_LOOP; ++it) {
        const int p0 = it * 6;
        // s = A @ nf via column lists; hi image only (s is fp16-rounded anyway)
        for (int r = 0; r < 16; ++r) {
            int l = warp * 16 + r;
            const uint8_t* cl = colb + l * 32;
            int cnt = cntp[l];
            float a0 = 0.f, a1 = 0.f, a2 = 0.f, a3 = 0.f;
#pragma unroll 2
            for (int j = 0; j < cnt; ++j) {
                int c = cl[j];
                uint2 vh = *(uint2*)(nfh + baddr(c, lane * 4));
                float2 h0 = upk2(vh.x), h1 = upk2(vh.y);
                a0 += h0.x; a1 += h0.y; a2 += h1.x; a3 += h1.y;
            }
            uint32_t off = baddr(l, lane * 4);
            *(uint2*)(shh + off) = make_uint2(pack_h2(a0, a1), pack_h2(a2, a3));
        }
        // ---- r = sigmoid(s@G_r + nf@Whh_r + deg*u + b)  [tanh.approx] ----
#pragma unroll
        for (int i = 0; i < 64; ++i) acc[i] = 0.f;
        consume_part(p0+0, A_SH,  0, false, acc, sb32, tid, mrow, ncol, lane);
        consume_part(p0+1, A_NFH, 0, false, acc, sb32, tid, mrow, ncol, lane);
#pragma unroll
        for (int mi = 0; mi < 2; ++mi)
#pragma unroll
            for (int ni = 0; ni < 8; ++ni)
#pragma unroll
                for (int q = 0; q < 4; ++q) {
                    int idx = (mi*8+ni)*4+q, col = tcol0 + ni*8 + (q&1);
                    gate[idx] = fsiga(acc[idx] + dgv[mi*2+(q>>1)]*sup[col] + bihp[col] + bhhp[col]);
                }
        // ---- n: acc = nf@Whh_n; gate *= (acc+bhh_n); acc = s@G_n; n = tanh.approx(...) ----
#pragma unroll
        for (int i = 0; i < 64; ++i) acc[i] = 0.f;
        consume_part(p0+2, A_NFH, 0, false, acc, sb32, tid, mrow, ncol, lane);
#pragma unroll
        for (int mi = 0; mi < 2; ++mi)
#pragma unroll
            for (int ni = 0; ni < 8; ++ni)
#pragma unroll
                for (int q = 0; q < 4; ++q) {
                    int idx = (mi*8+ni)*4+q, col = tcol0 + ni*8 + (q&1);
                    gate[idx] *= (acc[idx] + bhhp[256 + col]);
                }
#pragma unroll
        for (int i = 0; i < 64; ++i) acc[i] = 0.f;
        consume_part(p0+3, A_SH, 0, false, acc, sb32, tid, mrow, ncol, lane);
#pragma unroll
        for (int mi = 0; mi < 2; ++mi)
#pragma unroll
            for (int ni = 0; ni < 8; ++ni)
#pragma unroll
                for (int q = 0; q < 4; ++q) {
                    int idx = (mi*8+ni)*4+q, col = tcol0 + ni*8 + (q&1);
                    gate[idx] = tanha(acc[idx] + dgv[mi*2+(q>>1)]*sup[256+col] + bihp[256+col] + gate[idx]);
                }
        // ---- z + update (z now tanh.approx too; validated by r/n delta of +1.1e-5) ----
#pragma unroll
        for (int i = 0; i < 64; ++i) acc[i] = 0.f;
        consume_part(p0+4, A_SH,  0, false, acc, sb32, tid, mrow, ncol, lane);
        consume_part(p0+5, A_NFH, 0, false, acc, sb32, tid, mrow, ncol, lane);
#pragma unroll
        for (int mi = 0; mi < 2; ++mi)
#pragma unroll
            for (int ni = 0; ni < 8; ++ni)
#pragma unroll
                for (int qr = 0; qr < 2; ++qr) {
                    int row = trow0 + mi*16 + qr*8, colp = tcol0 + ni*8;
                    int i0 = (mi*8+ni)*4 + qr*2;
                    float dg = dgv[mi*2+qr];
                    float z0 = fsiga(acc[i0]   + dg*sup[128+colp]   + bihp[128+colp]   + bhhp[128+colp]);
                    float z1 = fsiga(acc[i0+1] + dg*sup[128+colp+1] + bihp[128+colp+1] + bhhp[128+colp+1]);
                    uint32_t off = baddr(row, colp);
                    float2 oh = upk2(*(uint32_t*)(nfh + off)), ol = upk2(*(uint32_t*)(nfl + off));
                    float o0 = oh.x + ol.x, o1 = oh.y + ol.y;
                    float n0 = gate[i0], n1 = gate[i0+1];
                    float w0 = n0 + z0 * (o0 - n0), w1 = n1 + z1 * (o1 - n1);
                    uint32_t lo, hi = pack_split(w0, w1, lo);
                    *(uint32_t*)(nfh + off) = hi;
                    *(uint32_t*)(nfl + off) = lo;
                }
        __syncthreads();   // nf ready for next gather / MLP
    }

    // ---- MLP (3-pass, precise activations): h1 = tanh(nf@mW1^T + b1) ----
#pragma unroll
    for (int i = 0; i < 64; ++i) acc[i] = 0.f;
    consume_part(60, A_NFH, A_NFL, true,  acc, sb32, tid, mrow, ncol, lane);  // mW1 hi
    consume_part(61, A_NFH, 0,     false, acc, sb32, tid, mrow, ncol, lane);  // mW1 lo
#pragma unroll
    for (int mi = 0; mi < 2; ++mi)
#pragma unroll
        for (int ni = 0; ni < 8; ++ni)
#pragma unroll
            for (int qr = 0; qr < 2; ++qr) {
                int row = trow0 + mi*16 + qr*8, colp = tcol0 + ni*8;
                int i0 = (mi*8+ni)*4 + qr*2;
                float v0 = ftanh(acc[i0]   + mb1p[colp]);
                float v1 = ftanh(acc[i0+1] + mb1p[colp+1]);
                uint32_t lo, hi = pack_split(v0, v1, lo);
                uint32_t off = baddr(row, colp);
                *(uint32_t*)(shh + off) = hi;    // h1 hi
                *(uint32_t*)(nfl + off) = lo;    // h1 lo (nf dead now)
            }
#pragma unroll
    for (int i = 0; i < 64; ++i) acc[i] = 0.f;
    consume_part(62, A_SH, A_NFL, true,  acc, sb32, tid, mrow, ncol, lane);   // mW2 hi
    consume_part(63, A_SH, 0,     false, acc, sb32, tid, mrow, ncol, lane);   // mW2 lo
    {
        float rsum[4] = {0.f, 0.f, 0.f, 0.f};
#pragma unroll
        for (int mi = 0; mi < 2; ++mi)
#pragma unroll
            for (int ni = 0; ni < 8; ++ni)
#pragma unroll
                for (int q = 0; q < 4; ++q) {
                    int idx = (mi*8+ni)*4+q, col = tcol0 + ni*8 + (q&1);
                    rsum[mi*2+(q>>1)] += ftanh(acc[idx] + mb2p[col]) * w3p[col];
                }
#pragma unroll
        for (int k = 0; k < 4; ++k) {
            rsum[k] += __shfl_xor_sync(0xFFFFFFFFu, rsum[k], 1);
            rsum[k] += __shfl_xor_sync(0xFFFFFFFFu, rsum[k], 2);
        }
        if ((lane & 3) == 0) {
#pragma unroll
            for (int mi = 0; mi < 2; ++mi)
#pragma unroll
                for (int qr = 0; qr < 2; ++qr)
                    redp[warpN * 128 + trow0 + mi*16 + qr*8] = rsum[mi*2+qr];
        }
    }
    __syncthreads();
    if (tid < 128)
        out[bs_idx * 128 + tid] = ftanh(redp[tid] + redp[128 + tid] + mb3[0]);
}

extern "C" void kernel_launch(void* const* d_in, const int* in_sizes, int n_in,
                              void* d_out, int out_size) {
    const int*   input_var = (const int*)  d_in[0];
    const float* adjacency = (const float*)d_in[1];
    const float* emb       = (const float*)d_in[2];
    const float* gnn_w     = (const float*)d_in[3];
    const float* gnn_b     = (const float*)d_in[4];
    const float* W_ih      = (const float*)d_in[5];
    const float* W_hh      = (const float*)d_in[6];
    const float* b_ih      = (const float*)d_in[7];
    const float* b_hh      = (const float*)d_in[8];
    const float* mW1       = (const float*)d_in[9];
    const float* mb1       = (const float*)d_in[10];
    const float* mW2       = (const float*)d_in[11];
    const float* mb2       = (const float*)d_in[12];
    const float* mW3       = (const float*)d_in[13];
    const float* mb3       = (const float*)d_in[14];
    float* out = (float*)d_out;

    prep_g<<<192, 256>>>(gnn_w, W_ih, gnn_b);
    prep_w<<<320, 256>>>(W_hh, mW1, mW2);

    cudaFuncSetAttribute(gnn_main, cudaFuncAttributeMaxDynamicSharedMemorySize, SMEM_TOTAL);
    gnn_main<<<NBS, 256, SMEM_TOTAL>>>(input_var, adjacency, emb,
                                       b_ih, b_hh, mb1, mb2, mW3, mb3, out);
}